// round 1
// baseline (speedup 1.0000x reference)
#include <cuda_runtime.h>
#include <math.h>

#define BATCH   4
#define NSEQ    2048
#define CDIM    1024
#define NHEADS  16
#define HDIM    64
#define MTOT    (BATCH * NSEQ)   // 8192

// Scratch (allocation-free rule: __device__ globals)
__device__ float g_Q[BATCH * NHEADS * NSEQ * HDIM];   // [B,H,N,D]
__device__ float g_K[BATCH * NHEADS * NSEQ * HDIM];
__device__ float g_V[BATCH * NHEADS * NSEQ * HDIM];
__device__ float g_att[MTOT * CDIM];                  // [B,N,C]

// ---------------------------------------------------------------------------
// SGEMM: out = A[M,K] @ W[K,N] + bias[N]
// 128x128 block tile, BK=8, 256 threads, 8x8 micro-tile (4+4 interleaved at
// stride 64 for conflict-free float4 shared loads).
// MODE 0: out row-major [M,N]
// MODE 1: out scattered to QKV layout [B,H,N,D] (row m -> (b,n), col c -> (h,d))
// ---------------------------------------------------------------------------
template <int MODE>
__global__ __launch_bounds__(256)
void sgemm128(const float* __restrict__ A, const float* __restrict__ W,
              const float* __restrict__ bias, float* __restrict__ out,
              int Mdim, int Ndim, int Kdim)
{
    __shared__ float As[8][128];
    __shared__ float Bs[8][128];

    const int tid = threadIdx.x;
    const int tx = tid & 15;
    const int ty = tid >> 4;

    const int row0 = blockIdx.y * 128;
    const int col0 = blockIdx.x * 128;

    // load assignments
    const int arow = tid >> 1;            // 0..127
    const int acol = (tid & 1) * 4;       // 0 or 4
    const int brow = tid >> 5;            // 0..7
    const int bcol = (tid & 31) * 4;      // 0..124

    const float* Aptr = A + (size_t)(row0 + arow) * Kdim + acol;
    const float* Bptr = W + (size_t)brow * Ndim + col0 + bcol;

    float acc[8][8];
#pragma unroll
    for (int i = 0; i < 8; i++)
#pragma unroll
        for (int j = 0; j < 8; j++) acc[i][j] = 0.f;

    for (int k0 = 0; k0 < Kdim; k0 += 8) {
        float4 av = *(const float4*)(Aptr + k0);
        float4 bv = *(const float4*)(Bptr + (size_t)k0 * Ndim);
        As[acol + 0][arow] = av.x;
        As[acol + 1][arow] = av.y;
        As[acol + 2][arow] = av.z;
        As[acol + 3][arow] = av.w;
        *(float4*)&Bs[brow][bcol] = bv;
        __syncthreads();

#pragma unroll
        for (int kk = 0; kk < 8; kk++) {
            float a[8], b[8];
            *(float4*)&a[0] = *(const float4*)&As[kk][ty * 4];
            *(float4*)&a[4] = *(const float4*)&As[kk][ty * 4 + 64];
            *(float4*)&b[0] = *(const float4*)&Bs[kk][tx * 4];
            *(float4*)&b[4] = *(const float4*)&Bs[kk][tx * 4 + 64];
#pragma unroll
            for (int i = 0; i < 8; i++)
#pragma unroll
                for (int j = 0; j < 8; j++)
                    acc[i][j] += a[i] * b[j];
        }
        __syncthreads();
    }

    // epilogue: rows = row0 + ty*4 + {0..3} and +64; cols similarly with tx
#pragma unroll
    for (int ih = 0; ih < 2; ih++) {
#pragma unroll
        for (int ii = 0; ii < 4; ii++) {
            const int i = ih * 4 + ii;
            const int r = row0 + ty * 4 + ii + ih * 64;
#pragma unroll
            for (int jh = 0; jh < 2; jh++) {
                const int cbase = col0 + jh * 64 + tx * 4;
                float4 v;
                v.x = acc[i][jh * 4 + 0] + bias[cbase + 0];
                v.y = acc[i][jh * 4 + 1] + bias[cbase + 1];
                v.z = acc[i][jh * 4 + 2] + bias[cbase + 2];
                v.w = acc[i][jh * 4 + 3] + bias[cbase + 3];
                if (MODE == 0) {
                    *(float4*)(out + (size_t)r * Ndim + cbase) = v;
                } else {
                    const int b = r >> 11;          // r / NSEQ
                    const int n = r & (NSEQ - 1);
                    const int h = cbase >> 6;       // cbase / HDIM
                    const int d = cbase & (HDIM - 1);
                    const size_t off =
                        ((size_t)(b * NHEADS + h) * NSEQ + n) * HDIM + d;
                    *(float4*)(out + off) = v;
                }
            }
        }
    }
}

// ---------------------------------------------------------------------------
// Flash attention (fp32): one thread per q-row, 128 q-rows per block.
// K/V tiles of 64 rows staged in smem; scores staged in diagonally-swizzled
// smem Ps (conflict-free); online softmax.
// Writes result directly to [B,N,C] layout for the O projection.
// ---------------------------------------------------------------------------
__global__ __launch_bounds__(128)
void attention_kernel(const float* __restrict__ Qg, const float* __restrict__ Kg,
                      const float* __restrict__ Vg, float* __restrict__ att)
{
    extern __shared__ __align__(16) float sm[];
    float* Ks = sm;              // 64*64
    float* Vs = sm + 4096;       // 64*64
    float* Ps = sm + 8192;       // 128*64 (swizzled)

    const int bh  = blockIdx.y;             // 0..63  (b*16 + h)
    const int tid = threadIdx.x;            // 0..127
    const int q   = blockIdx.x * 128 + tid; // global q row

    const float* Q = Qg + (size_t)bh * NSEQ * HDIM;
    const float* K = Kg + (size_t)bh * NSEQ * HDIM;
    const float* V = Vg + (size_t)bh * NSEQ * HDIM;

    float qreg[HDIM];
#pragma unroll
    for (int d = 0; d < HDIM; d++)
        qreg[d] = Q[(size_t)q * HDIM + d] * 0.125f;  // 1/sqrt(64)

    float o[HDIM];
#pragma unroll
    for (int d = 0; d < HDIM; d++) o[d] = 0.f;
    float mmax = -INFINITY;
    float lsum = 0.f;

    for (int kt = 0; kt < NSEQ; kt += 64) {
        __syncthreads();
        // stage K,V tile: 64 rows x 16 float4 each
        for (int i = tid; i < 64 * 16; i += 128) {
            const int r  = i >> 4;
            const int c4 = i & 15;
            ((float4*)(Ks + r * 64))[c4] =
                ((const float4*)(K + (size_t)(kt + r) * HDIM))[c4];
            ((float4*)(Vs + r * 64))[c4] =
                ((const float4*)(V + (size_t)(kt + r) * HDIM))[c4];
        }
        __syncthreads();

        // phase 1: scores + tile max
        float tmax = -INFINITY;
#pragma unroll 4
        for (int kk = 0; kk < 64; kk++) {
            float s = 0.f;
            const float* krow = Ks + kk * 64;
#pragma unroll
            for (int d = 0; d < HDIM; d++) s += qreg[d] * krow[d];
            Ps[tid * 64 + ((kk + tid) & 63)] = s;
            tmax = fmaxf(tmax, s);
        }

        const float mnew  = fmaxf(mmax, tmax);
        const float alpha = __expf(mmax - mnew);
        lsum *= alpha;
#pragma unroll
        for (int d = 0; d < HDIM; d++) o[d] *= alpha;
        mmax = mnew;

        // phase 2: exp + accumulate P@V
#pragma unroll 2
        for (int kk = 0; kk < 64; kk++) {
            const float p = __expf(Ps[tid * 64 + ((kk + tid) & 63)] - mnew);
            lsum += p;
            const float* vrow = Vs + kk * 64;
#pragma unroll
            for (int d = 0; d < HDIM; d++) o[d] += p * vrow[d];
        }
    }

    const float inv = 1.f / lsum;
    const int b = bh >> 4;
    const int h = bh & 15;
    float* dst = att + ((size_t)(b * NSEQ + q)) * CDIM + h * HDIM;
#pragma unroll
    for (int d = 0; d < HDIM; d += 4) {
        float4 v;
        v.x = o[d + 0] * inv;
        v.y = o[d + 1] * inv;
        v.z = o[d + 2] * inv;
        v.w = o[d + 3] * inv;
        *(float4*)(dst + d) = v;
    }
}

// ---------------------------------------------------------------------------

extern "C" void kernel_launch(void* const* d_in, const int* in_sizes, int n_in,
                              void* d_out, int out_size)
{
    const float* x  = (const float*)d_in[0];
    const float* Wq = (const float*)d_in[1];
    const float* bq = (const float*)d_in[2];
    const float* Wk = (const float*)d_in[3];
    const float* bk = (const float*)d_in[4];
    const float* Wv = (const float*)d_in[5];
    const float* bv = (const float*)d_in[6];
    const float* Wo = (const float*)d_in[7];
    const float* bo = (const float*)d_in[8];
    float* out = (float*)d_out;

    float *Qp, *Kp, *Vp, *Ap;
    cudaGetSymbolAddress((void**)&Qp, g_Q);
    cudaGetSymbolAddress((void**)&Kp, g_K);
    cudaGetSymbolAddress((void**)&Vp, g_V);
    cudaGetSymbolAddress((void**)&Ap, g_att);

    const dim3 ggrid(CDIM / 128, MTOT / 128);  // (8, 64)

    // Q/K/V projections with fused transpose-to-[B,H,N,D]
    sgemm128<1><<<ggrid, 256>>>(x, Wq, bq, Qp, MTOT, CDIM, CDIM);
    sgemm128<1><<<ggrid, 256>>>(x, Wk, bk, Kp, MTOT, CDIM, CDIM);
    sgemm128<1><<<ggrid, 256>>>(x, Wv, bv, Vp, MTOT, CDIM, CDIM);

    // attention
    const int att_smem = (4096 + 4096 + 128 * 64) * (int)sizeof(float); // 64 KB
    cudaFuncSetAttribute(attention_kernel,
                         cudaFuncAttributeMaxDynamicSharedMemorySize, att_smem);
    attention_kernel<<<dim3(NSEQ / 128, BATCH * NHEADS), 128, att_smem>>>(
        Qp, Kp, Vp, Ap);

    // output projection
    sgemm128<0><<<ggrid, 256>>>(Ap, Wo, bo, out, MTOT, CDIM, CDIM);
}

// round 2
// speedup vs baseline: 2.0385x; 2.0385x over previous
#include <cuda_runtime.h>
#include <math.h>
#include <stdint.h>

#define BATCH   4
#define NSEQ    2048
#define CDIM    1024
#define NHEADS  16
#define HDIM    64
#define MTOT    (BATCH * NSEQ)   // 8192

// Scratch (allocation-free rule: __device__ globals)
__device__ float g_Q[BATCH * NHEADS * NSEQ * HDIM];   // [B,H,N,D]
__device__ float g_K[BATCH * NHEADS * NSEQ * HDIM];
__device__ float g_V[BATCH * NHEADS * NSEQ * HDIM];
__device__ float g_att[MTOT * CDIM];                  // [B,N,C]

__device__ __forceinline__ uint32_t f2tf(float f) {
    uint32_t u;
    asm("cvt.rna.tf32.f32 %0, %1;" : "=r"(u) : "f"(f));
    return u;
}
__device__ __forceinline__ float fex2(float x) {
    float r;
    asm("ex2.approx.f32 %0, %1;" : "=f"(r) : "f"(x));
    return r;
}
__device__ __forceinline__ void mma8(float* c, const uint32_t* a,
                                     uint32_t b0, uint32_t b1) {
    asm volatile(
        "mma.sync.aligned.m16n8k8.row.col.f32.tf32.tf32.f32 "
        "{%0,%1,%2,%3}, {%4,%5,%6,%7}, {%8,%9}, {%0,%1,%2,%3};"
        : "+f"(c[0]), "+f"(c[1]), "+f"(c[2]), "+f"(c[3])
        : "r"(a[0]), "r"(a[1]), "r"(a[2]), "r"(a[3]), "r"(b0), "r"(b1));
}

// ---------------------------------------------------------------------------
// TF32 tensor-core GEMM: out = A[M,1024] @ W[1024,1024] + bias
// 128x128x16 block tile, 256 threads (8 warps), warp tile 64x32.
// As: [k][m] stride 136 (ktile=16, scatter-stored, conflict-free).
// Bs: [k][n] stride 136 (row-copied, conflict-free frag loads).
// MODE 0: row-major [M,N]   MODE 1: scatter to [B,H,N,D]
// ---------------------------------------------------------------------------
#define GS 136

template <int MODE>
__global__ __launch_bounds__(256, 1)
void gemm_tf32(const float* __restrict__ A, const float* __restrict__ W,
               const float* __restrict__ bias, float* __restrict__ out)
{
    __shared__ uint32_t As[16 * GS];
    __shared__ uint32_t Bs[16 * GS];

    const int tid = threadIdx.x, lane = tid & 31, warp = tid >> 5;
    const int g = lane >> 2, t = lane & 3;
    const int wm = (warp & 1) * 64, wn = (warp >> 1) * 32;
    const int row0 = blockIdx.y * 128, col0 = blockIdx.x * 128;

    const int am = tid & 127, ak = (tid >> 7) * 8;
    const int bk = tid >> 4,  bn = (tid & 15) * 8;
    const float* Ag = A + (size_t)(row0 + am) * CDIM + ak;
    const float* Bg = W + (size_t)bk * CDIM + col0 + bn;

    float4 ra0 = *(const float4*)(Ag);
    float4 ra1 = *(const float4*)(Ag + 4);
    float4 rb0 = *(const float4*)(Bg);
    float4 rb1 = *(const float4*)(Bg + 4);

    float acc[4][4][4];
#pragma unroll
    for (int i = 0; i < 4; i++)
#pragma unroll
        for (int j = 0; j < 4; j++)
#pragma unroll
            for (int v = 0; v < 4; v++) acc[i][j][v] = 0.f;

    for (int k0 = 0; k0 < CDIM; k0 += 16) {
        // stage current tile (cvt to tf32)
        As[(ak + 0) * GS + am] = f2tf(ra0.x);
        As[(ak + 1) * GS + am] = f2tf(ra0.y);
        As[(ak + 2) * GS + am] = f2tf(ra0.z);
        As[(ak + 3) * GS + am] = f2tf(ra0.w);
        As[(ak + 4) * GS + am] = f2tf(ra1.x);
        As[(ak + 5) * GS + am] = f2tf(ra1.y);
        As[(ak + 6) * GS + am] = f2tf(ra1.z);
        As[(ak + 7) * GS + am] = f2tf(ra1.w);
        uint4 b04 = make_uint4(f2tf(rb0.x), f2tf(rb0.y), f2tf(rb0.z), f2tf(rb0.w));
        uint4 b14 = make_uint4(f2tf(rb1.x), f2tf(rb1.y), f2tf(rb1.z), f2tf(rb1.w));
        *(uint4*)&Bs[bk * GS + bn]     = b04;
        *(uint4*)&Bs[bk * GS + bn + 4] = b14;
        __syncthreads();

        // prefetch next tile into registers (overlaps with compute)
        if (k0 + 16 < CDIM) {
            ra0 = *(const float4*)(Ag + k0 + 16);
            ra1 = *(const float4*)(Ag + k0 + 20);
            rb0 = *(const float4*)(Bg + (size_t)(k0 + 16) * CDIM);
            rb1 = *(const float4*)(Bg + (size_t)(k0 + 16) * CDIM + 4);
        }

#pragma unroll
        for (int ks = 0; ks < 2; ks++) {
            const int kb = ks * 8;
            uint32_t af[4][4];
#pragma unroll
            for (int mt = 0; mt < 4; mt++) {
                const int m = wm + mt * 16 + g;
                af[mt][0] = As[(kb + t) * GS + m];
                af[mt][1] = As[(kb + t) * GS + m + 8];
                af[mt][2] = As[(kb + t + 4) * GS + m];
                af[mt][3] = As[(kb + t + 4) * GS + m + 8];
            }
#pragma unroll
            for (int nt = 0; nt < 4; nt++) {
                const int n = wn + nt * 8 + g;
                const uint32_t b0 = Bs[(kb + t) * GS + n];
                const uint32_t b1 = Bs[(kb + t + 4) * GS + n];
#pragma unroll
                for (int mt = 0; mt < 4; mt++) mma8(acc[mt][nt], af[mt], b0, b1);
            }
        }
        __syncthreads();
    }

    // epilogue: bias + store
#pragma unroll
    for (int mt = 0; mt < 4; mt++) {
        const int r = row0 + wm + mt * 16 + g;
#pragma unroll
        for (int nt = 0; nt < 4; nt++) {
            const int c = col0 + wn + nt * 8 + 2 * t;
            const float bx = bias[c], by = bias[c + 1];
            float2 v0 = make_float2(acc[mt][nt][0] + bx, acc[mt][nt][1] + by);
            float2 v1 = make_float2(acc[mt][nt][2] + bx, acc[mt][nt][3] + by);
            if (MODE == 0) {
                *(float2*)(out + (size_t)r * CDIM + c) = v0;
                *(float2*)(out + (size_t)(r + 8) * CDIM + c) = v1;
            } else {
                const int h = c >> 6, d = c & 63;
                const int bi = r >> 11, ni = r & (NSEQ - 1);
                *(float2*)(out + ((size_t)(bi * NHEADS + h) * NSEQ + ni) * HDIM + d) = v0;
                *(float2*)(out + ((size_t)(bi * NHEADS + h) * NSEQ + ni + 8) * HDIM + d) = v1;
            }
        }
    }
}

// ---------------------------------------------------------------------------
// TF32 tensor-core flash attention.
// Block: 256 q-rows, one (b,h); 8 warps, each warp owns 32 q (2 m-tiles).
// K-tiles of 64 keys. All smem row-major with stride 72 (=8 mod 32 ->
// conflict-free fragment loads for both A-frag and B-frag patterns).
// Online softmax in base 2 (scale*log2e folded into Q staging).
// ---------------------------------------------------------------------------
#define ASTR 72

__global__ __launch_bounds__(256, 1)
void attn_tf32(const float* __restrict__ Qg, const float* __restrict__ Kg,
               const float* __restrict__ Vg, float* __restrict__ att)
{
    extern __shared__ uint32_t sm[];
    uint32_t* Qs = sm;                      // [256][72]
    uint32_t* Ks = Qs + 256 * ASTR;         // [64][72]  (key-major)
    uint32_t* Vs = Ks + 64 * ASTR;          // [64][72]  (key-major)
    uint32_t* Ps = Vs + 64 * ASTR;          // [256][72] (q-major)

    const int tid = threadIdx.x, lane = tid & 31, warp = tid >> 5;
    const int g = lane >> 2, t = lane & 3;
    const int bh = blockIdx.y;
    const int qb = blockIdx.x * 256;

    const float* Q = Qg + (size_t)bh * NSEQ * HDIM;
    const float* K = Kg + (size_t)bh * NSEQ * HDIM;
    const float* V = Vg + (size_t)bh * NSEQ * HDIM;

    // stage Q once: scaled by (1/sqrt(D)) * log2(e), tf32
    const float qscale = 0.125f * 1.4426950408889634f;
    for (int idx = tid; idx < 256 * 16; idx += 256) {
        const int m = idx >> 4, d4 = (idx & 15) * 4;
        float4 v = *(const float4*)(Q + (size_t)(qb + m) * HDIM + d4);
        uint4 u = make_uint4(f2tf(v.x * qscale), f2tf(v.y * qscale),
                             f2tf(v.z * qscale), f2tf(v.w * qscale));
        *(uint4*)&Qs[m * ASTR + d4] = u;
    }

    float o[2][8][4];
#pragma unroll
    for (int a = 0; a < 2; a++)
#pragma unroll
        for (int b = 0; b < 8; b++)
#pragma unroll
            for (int c = 0; c < 4; c++) o[a][b][c] = 0.f;
    float mrow[2][2] = {{-1e30f, -1e30f}, {-1e30f, -1e30f}};
    float lrow[2][2] = {{0.f, 0.f}, {0.f, 0.f}};

    for (int kt = 0; kt < NSEQ; kt += 64) {
        __syncthreads();   // previous tile fully consumed
        // stage K,V tile (tf32)
        for (int idx = tid; idx < 64 * 16; idx += 256) {
            const int key = idx >> 4, d4 = (idx & 15) * 4;
            float4 kv = *(const float4*)(K + (size_t)(kt + key) * HDIM + d4);
            float4 vv = *(const float4*)(V + (size_t)(kt + key) * HDIM + d4);
            *(uint4*)&Ks[key * ASTR + d4] =
                make_uint4(f2tf(kv.x), f2tf(kv.y), f2tf(kv.z), f2tf(kv.w));
            *(uint4*)&Vs[key * ASTR + d4] =
                make_uint4(f2tf(vv.x), f2tf(vv.y), f2tf(vv.z), f2tf(vv.w));
        }
        __syncthreads();

        // ---- S = Q @ K^T (scaled, base-2) ----
        float s[2][8][4];
#pragma unroll
        for (int a = 0; a < 2; a++)
#pragma unroll
            for (int b = 0; b < 8; b++)
#pragma unroll
                for (int c = 0; c < 4; c++) s[a][b][c] = 0.f;

#pragma unroll
        for (int ks = 0; ks < 8; ks++) {
            const int kd = ks * 8;
            uint32_t aq[2][4];
#pragma unroll
            for (int mt = 0; mt < 2; mt++) {
                const int qr = warp * 32 + mt * 16 + g;
                aq[mt][0] = Qs[qr * ASTR + kd + t];
                aq[mt][1] = Qs[(qr + 8) * ASTR + kd + t];
                aq[mt][2] = Qs[qr * ASTR + kd + t + 4];
                aq[mt][3] = Qs[(qr + 8) * ASTR + kd + t + 4];
            }
#pragma unroll
            for (int nt = 0; nt < 8; nt++) {
                const uint32_t b0 = Ks[(nt * 8 + g) * ASTR + kd + t];
                const uint32_t b1 = Ks[(nt * 8 + g) * ASTR + kd + t + 4];
                mma8(s[0][nt], aq[0], b0, b1);
                mma8(s[1][nt], aq[1], b0, b1);
            }
        }

        // ---- online softmax + write P (tf32) to smem ----
#pragma unroll
        for (int mt = 0; mt < 2; mt++) {
            float tl = -1e30f, th = -1e30f;
#pragma unroll
            for (int nt = 0; nt < 8; nt++) {
                tl = fmaxf(tl, fmaxf(s[mt][nt][0], s[mt][nt][1]));
                th = fmaxf(th, fmaxf(s[mt][nt][2], s[mt][nt][3]));
            }
            tl = fmaxf(tl, __shfl_xor_sync(0xffffffffu, tl, 1));
            tl = fmaxf(tl, __shfl_xor_sync(0xffffffffu, tl, 2));
            th = fmaxf(th, __shfl_xor_sync(0xffffffffu, th, 1));
            th = fmaxf(th, __shfl_xor_sync(0xffffffffu, th, 2));

            const float mlo = fmaxf(mrow[mt][0], tl);
            const float mhi = fmaxf(mrow[mt][1], th);
            const float alo = fex2(mrow[mt][0] - mlo);
            const float ahi = fex2(mrow[mt][1] - mhi);
            mrow[mt][0] = mlo; mrow[mt][1] = mhi;
            lrow[mt][0] *= alo; lrow[mt][1] *= ahi;
#pragma unroll
            for (int dt = 0; dt < 8; dt++) {
                o[mt][dt][0] *= alo; o[mt][dt][1] *= alo;
                o[mt][dt][2] *= ahi; o[mt][dt][3] *= ahi;
            }
            const int qr = warp * 32 + mt * 16 + g;
#pragma unroll
            for (int nt = 0; nt < 8; nt++) {
                const float p0 = fex2(s[mt][nt][0] - mlo);
                const float p1 = fex2(s[mt][nt][1] - mlo);
                const float p2 = fex2(s[mt][nt][2] - mhi);
                const float p3 = fex2(s[mt][nt][3] - mhi);
                lrow[mt][0] += p0 + p1;
                lrow[mt][1] += p2 + p3;
                const int kc = nt * 8 + 2 * t;
                Ps[qr * ASTR + kc]           = f2tf(p0);
                Ps[qr * ASTR + kc + 1]       = f2tf(p1);
                Ps[(qr + 8) * ASTR + kc]     = f2tf(p2);
                Ps[(qr + 8) * ASTR + kc + 1] = f2tf(p3);
            }
        }
        __syncwarp();

        // ---- O += P @ V ----
#pragma unroll
        for (int ks = 0; ks < 8; ks++) {
            const int kk = ks * 8;
            uint32_t ap[2][4];
#pragma unroll
            for (int mt = 0; mt < 2; mt++) {
                const int qr = warp * 32 + mt * 16 + g;
                ap[mt][0] = Ps[qr * ASTR + kk + t];
                ap[mt][1] = Ps[(qr + 8) * ASTR + kk + t];
                ap[mt][2] = Ps[qr * ASTR + kk + t + 4];
                ap[mt][3] = Ps[(qr + 8) * ASTR + kk + t + 4];
            }
#pragma unroll
            for (int nt = 0; nt < 8; nt++) {
                const uint32_t b0 = Vs[(kk + t) * ASTR + nt * 8 + g];
                const uint32_t b1 = Vs[(kk + t + 4) * ASTR + nt * 8 + g];
                mma8(o[0][nt], ap[0], b0, b1);
                mma8(o[1][nt], ap[1], b0, b1);
            }
        }
    }

    // finalize: reduce row sums across the 4-lane group, normalize, store
    const int b = bh >> 4, h = bh & 15;
#pragma unroll
    for (int mt = 0; mt < 2; mt++) {
        float l0 = lrow[mt][0], l1 = lrow[mt][1];
        l0 += __shfl_xor_sync(0xffffffffu, l0, 1);
        l0 += __shfl_xor_sync(0xffffffffu, l0, 2);
        l1 += __shfl_xor_sync(0xffffffffu, l1, 1);
        l1 += __shfl_xor_sync(0xffffffffu, l1, 2);
        const float i0 = 1.f / l0, i1 = 1.f / l1;
        const int qg = qb + warp * 32 + mt * 16 + g;
#pragma unroll
        for (int nt = 0; nt < 8; nt++) {
            const int col = h * 64 + nt * 8 + 2 * t;
            float2 w0 = make_float2(o[mt][nt][0] * i0, o[mt][nt][1] * i0);
            float2 w1 = make_float2(o[mt][nt][2] * i1, o[mt][nt][3] * i1);
            *(float2*)(att + (size_t)(b * NSEQ + qg) * CDIM + col) = w0;
            *(float2*)(att + (size_t)(b * NSEQ + qg + 8) * CDIM + col) = w1;
        }
    }
}

// ---------------------------------------------------------------------------

extern "C" void kernel_launch(void* const* d_in, const int* in_sizes, int n_in,
                              void* d_out, int out_size)
{
    const float* x  = (const float*)d_in[0];
    const float* Wq = (const float*)d_in[1];
    const float* bq = (const float*)d_in[2];
    const float* Wk = (const float*)d_in[3];
    const float* bk = (const float*)d_in[4];
    const float* Wv = (const float*)d_in[5];
    const float* bv = (const float*)d_in[6];
    const float* Wo = (const float*)d_in[7];
    const float* bo = (const float*)d_in[8];
    float* out = (float*)d_out;

    float *Qp, *Kp, *Vp, *Ap;
    cudaGetSymbolAddress((void**)&Qp, g_Q);
    cudaGetSymbolAddress((void**)&Kp, g_K);
    cudaGetSymbolAddress((void**)&Vp, g_V);
    cudaGetSymbolAddress((void**)&Ap, g_att);

    const dim3 ggrid(CDIM / 128, MTOT / 128);  // (8, 64)

    gemm_tf32<1><<<ggrid, 256>>>(x, Wq, bq, Qp);
    gemm_tf32<1><<<ggrid, 256>>>(x, Wk, bk, Kp);
    gemm_tf32<1><<<ggrid, 256>>>(x, Wv, bv, Vp);

    const int att_smem = (256 * ASTR + 64 * ASTR + 64 * ASTR + 256 * ASTR) * 4;
    cudaFuncSetAttribute(attn_tf32,
                         cudaFuncAttributeMaxDynamicSharedMemorySize, att_smem);
    attn_tf32<<<dim3(NSEQ / 256, BATCH * NHEADS), 256, att_smem>>>(Qp, Kp, Vp, Ap);

    gemm_tf32<0><<<ggrid, 256>>>(Ap, Wo, bo, out);
}

// round 3
// speedup vs baseline: 2.4805x; 1.2168x over previous
#include <cuda_runtime.h>
#include <math.h>
#include <stdint.h>

#define BATCH   4
#define NSEQ    2048
#define CDIM    1024
#define NHEADS  16
#define HDIM    64
#define MTOT    (BATCH * NSEQ)   // 8192

// Scratch (allocation-free rule: __device__ globals)
__device__ float g_Q[BATCH * NHEADS * NSEQ * HDIM];   // [B,H,N,D]
__device__ float g_K[BATCH * NHEADS * NSEQ * HDIM];
__device__ float g_V[BATCH * NHEADS * NSEQ * HDIM];
__device__ float g_att[MTOT * CDIM];                  // [B,N,C]

__device__ __forceinline__ uint32_t f2tf(float f) {
    uint32_t u;
    asm("cvt.rna.tf32.f32 %0, %1;" : "=r"(u) : "f"(f));
    return u;
}
__device__ __forceinline__ float fex2(float x) {
    float r;
    asm("ex2.approx.f32 %0, %1;" : "=f"(r) : "f"(x));
    return r;
}
__device__ __forceinline__ void mma8(float* c, const uint32_t* a,
                                     uint32_t b0, uint32_t b1) {
    asm volatile(
        "mma.sync.aligned.m16n8k8.row.col.f32.tf32.tf32.f32 "
        "{%0,%1,%2,%3}, {%4,%5,%6,%7}, {%8,%9}, {%0,%1,%2,%3};"
        : "+f"(c[0]), "+f"(c[1]), "+f"(c[2]), "+f"(c[3])
        : "r"(a[0]), "r"(a[1]), "r"(a[2]), "r"(a[3]), "r"(b0), "r"(b1));
}

// ---------------------------------------------------------------------------
// TF32 tensor-core GEMM: out = A[M,1024] @ W[1024,1024] + bias
// 128x128x16 block tile, 256 threads (8 warps), warp tile 64x32.
// Double-buffered smem: one __syncthreads per k-tile, global-load latency
// hidden behind the 32 MMAs of the current tile.
// MODE 0: row-major [M,N]   MODE 1: scatter to [B,H,N,D]
// ---------------------------------------------------------------------------
#define GS 136

template <int MODE>
__global__ __launch_bounds__(256, 2)
void gemm_tf32(const float* __restrict__ A, const float* __restrict__ W,
               const float* __restrict__ bias, float* __restrict__ out)
{
    __shared__ uint32_t As[2][16 * GS];
    __shared__ uint32_t Bs[2][16 * GS];

    const int tid = threadIdx.x, lane = tid & 31, warp = tid >> 5;
    const int g = lane >> 2, t = lane & 3;
    const int wm = (warp & 1) * 64, wn = (warp >> 1) * 32;
    const int row0 = blockIdx.y * 128, col0 = blockIdx.x * 128;

    const int am = tid & 127, ak = (tid >> 7) * 8;
    const int bk = tid >> 4,  bn = (tid & 15) * 8;
    const float* Ag = A + (size_t)(row0 + am) * CDIM + ak;
    const float* Bg = W + (size_t)bk * CDIM + col0 + bn;

    float acc[4][4][4];
#pragma unroll
    for (int i = 0; i < 4; i++)
#pragma unroll
        for (int j = 0; j < 4; j++)
#pragma unroll
            for (int v = 0; v < 4; v++) acc[i][j][v] = 0.f;

    // prologue: load + stage tile 0
    float4 ra0 = *(const float4*)(Ag);
    float4 ra1 = *(const float4*)(Ag + 4);
    float4 rb0 = *(const float4*)(Bg);
    float4 rb1 = *(const float4*)(Bg + 4);
    As[0][(ak + 0) * GS + am] = f2tf(ra0.x);
    As[0][(ak + 1) * GS + am] = f2tf(ra0.y);
    As[0][(ak + 2) * GS + am] = f2tf(ra0.z);
    As[0][(ak + 3) * GS + am] = f2tf(ra0.w);
    As[0][(ak + 4) * GS + am] = f2tf(ra1.x);
    As[0][(ak + 5) * GS + am] = f2tf(ra1.y);
    As[0][(ak + 6) * GS + am] = f2tf(ra1.z);
    As[0][(ak + 7) * GS + am] = f2tf(ra1.w);
    *(uint4*)&Bs[0][bk * GS + bn] =
        make_uint4(f2tf(rb0.x), f2tf(rb0.y), f2tf(rb0.z), f2tf(rb0.w));
    *(uint4*)&Bs[0][bk * GS + bn + 4] =
        make_uint4(f2tf(rb1.x), f2tf(rb1.y), f2tf(rb1.z), f2tf(rb1.w));
    __syncthreads();

    int buf = 0;
    for (int k0 = 0; k0 < CDIM; k0 += 16) {
        const bool more = (k0 + 16 < CDIM);
        // issue global loads for next tile (latency hidden by compute below)
        if (more) {
            ra0 = *(const float4*)(Ag + k0 + 16);
            ra1 = *(const float4*)(Ag + k0 + 20);
            rb0 = *(const float4*)(Bg + (size_t)(k0 + 16) * CDIM);
            rb1 = *(const float4*)(Bg + (size_t)(k0 + 16) * CDIM + 4);
        }

        const uint32_t* Ab = As[buf];
        const uint32_t* Bb = Bs[buf];
#pragma unroll
        for (int ks = 0; ks < 2; ks++) {
            const int kb = ks * 8;
            uint32_t af[4][4];
#pragma unroll
            for (int mt = 0; mt < 4; mt++) {
                const int m = wm + mt * 16 + g;
                af[mt][0] = Ab[(kb + t) * GS + m];
                af[mt][1] = Ab[(kb + t) * GS + m + 8];
                af[mt][2] = Ab[(kb + t + 4) * GS + m];
                af[mt][3] = Ab[(kb + t + 4) * GS + m + 8];
            }
#pragma unroll
            for (int nt = 0; nt < 4; nt++) {
                const int n = wn + nt * 8 + g;
                const uint32_t b0 = Bb[(kb + t) * GS + n];
                const uint32_t b1 = Bb[(kb + t + 4) * GS + n];
#pragma unroll
                for (int mt = 0; mt < 4; mt++) mma8(acc[mt][nt], af[mt], b0, b1);
            }
        }

        if (more) {
            uint32_t* An = As[buf ^ 1];
            uint32_t* Bn = Bs[buf ^ 1];
            An[(ak + 0) * GS + am] = f2tf(ra0.x);
            An[(ak + 1) * GS + am] = f2tf(ra0.y);
            An[(ak + 2) * GS + am] = f2tf(ra0.z);
            An[(ak + 3) * GS + am] = f2tf(ra0.w);
            An[(ak + 4) * GS + am] = f2tf(ra1.x);
            An[(ak + 5) * GS + am] = f2tf(ra1.y);
            An[(ak + 6) * GS + am] = f2tf(ra1.z);
            An[(ak + 7) * GS + am] = f2tf(ra1.w);
            *(uint4*)&Bn[bk * GS + bn] =
                make_uint4(f2tf(rb0.x), f2tf(rb0.y), f2tf(rb0.z), f2tf(rb0.w));
            *(uint4*)&Bn[bk * GS + bn + 4] =
                make_uint4(f2tf(rb1.x), f2tf(rb1.y), f2tf(rb1.z), f2tf(rb1.w));
            __syncthreads();
            buf ^= 1;
        }
    }

    // epilogue: bias + store
#pragma unroll
    for (int mt = 0; mt < 4; mt++) {
        const int r = row0 + wm + mt * 16 + g;
#pragma unroll
        for (int nt = 0; nt < 4; nt++) {
            const int c = col0 + wn + nt * 8 + 2 * t;
            const float bx = bias[c], by = bias[c + 1];
            float2 v0 = make_float2(acc[mt][nt][0] + bx, acc[mt][nt][1] + by);
            float2 v1 = make_float2(acc[mt][nt][2] + bx, acc[mt][nt][3] + by);
            if (MODE == 0) {
                *(float2*)(out + (size_t)r * CDIM + c) = v0;
                *(float2*)(out + (size_t)(r + 8) * CDIM + c) = v1;
            } else {
                const int h = c >> 6, d = c & 63;
                const int bi = r >> 11, ni = r & (NSEQ - 1);
                *(float2*)(out + ((size_t)(bi * NHEADS + h) * NSEQ + ni) * HDIM + d) = v0;
                *(float2*)(out + ((size_t)(bi * NHEADS + h) * NSEQ + ni + 8) * HDIM + d) = v1;
            }
        }
    }
}

// ---------------------------------------------------------------------------
// TF32 tensor-core flash attention.
// Block: 128 q-rows, one (b,h); 8 warps, each warp owns 16 q (one m16 tile).
// smem = 110.6 KB -> 2 CTAs/SM (occupancy doubled vs R1; one CTA's softmax
// ALU phase overlaps the other's MMA phase).
// K-tiles of 64 keys. All smem stride 72 (conflict-free frag loads).
// Online softmax in base 2 (scale*log2e folded into Q staging).
// ---------------------------------------------------------------------------
#define ASTR 72

__global__ __launch_bounds__(256, 2)
void attn_tf32(const float* __restrict__ Qg, const float* __restrict__ Kg,
               const float* __restrict__ Vg, float* __restrict__ att)
{
    extern __shared__ uint32_t sm[];
    uint32_t* Qs = sm;                      // [128][72]
    uint32_t* Ks = Qs + 128 * ASTR;         // [64][72]  (key-major)
    uint32_t* Vs = Ks + 64 * ASTR;          // [64][72]  (key-major)
    uint32_t* Ps = Vs + 64 * ASTR;          // [128][72] (q-major)

    const int tid = threadIdx.x, lane = tid & 31, warp = tid >> 5;
    const int g = lane >> 2, t = lane & 3;
    const int bh = blockIdx.y;
    const int qb = blockIdx.x * 128;

    const float* Q = Qg + (size_t)bh * NSEQ * HDIM;
    const float* K = Kg + (size_t)bh * NSEQ * HDIM;
    const float* V = Vg + (size_t)bh * NSEQ * HDIM;

    // stage Q once: scaled by (1/sqrt(D)) * log2(e), tf32
    const float qscale = 0.125f * 1.4426950408889634f;
    for (int idx = tid; idx < 128 * 16; idx += 256) {
        const int m = idx >> 4, d4 = (idx & 15) * 4;
        float4 v = *(const float4*)(Q + (size_t)(qb + m) * HDIM + d4);
        *(uint4*)&Qs[m * ASTR + d4] =
            make_uint4(f2tf(v.x * qscale), f2tf(v.y * qscale),
                       f2tf(v.z * qscale), f2tf(v.w * qscale));
    }

    float o[8][4];
#pragma unroll
    for (int b = 0; b < 8; b++)
#pragma unroll
        for (int c = 0; c < 4; c++) o[b][c] = 0.f;
    float mrow[2] = {-1e30f, -1e30f};
    float lrow[2] = {0.f, 0.f};

    const int qr = warp * 16 + g;   // this thread's q-row pair base (smem)

    for (int kt = 0; kt < NSEQ; kt += 64) {
        __syncthreads();   // previous tile fully consumed
        for (int idx = tid; idx < 64 * 16; idx += 256) {
            const int key = idx >> 4, d4 = (idx & 15) * 4;
            float4 kv = *(const float4*)(K + (size_t)(kt + key) * HDIM + d4);
            float4 vv = *(const float4*)(V + (size_t)(kt + key) * HDIM + d4);
            *(uint4*)&Ks[key * ASTR + d4] =
                make_uint4(f2tf(kv.x), f2tf(kv.y), f2tf(kv.z), f2tf(kv.w));
            *(uint4*)&Vs[key * ASTR + d4] =
                make_uint4(f2tf(vv.x), f2tf(vv.y), f2tf(vv.z), f2tf(vv.w));
        }
        __syncthreads();

        // ---- S = Q @ K^T (scaled, base-2) ----
        float s[8][4];
#pragma unroll
        for (int b = 0; b < 8; b++)
#pragma unroll
            for (int c = 0; c < 4; c++) s[b][c] = 0.f;

#pragma unroll
        for (int ks = 0; ks < 8; ks++) {
            const int kd = ks * 8;
            uint32_t aq[4];
            aq[0] = Qs[qr * ASTR + kd + t];
            aq[1] = Qs[(qr + 8) * ASTR + kd + t];
            aq[2] = Qs[qr * ASTR + kd + t + 4];
            aq[3] = Qs[(qr + 8) * ASTR + kd + t + 4];
#pragma unroll
            for (int nt = 0; nt < 8; nt++) {
                const uint32_t b0 = Ks[(nt * 8 + g) * ASTR + kd + t];
                const uint32_t b1 = Ks[(nt * 8 + g) * ASTR + kd + t + 4];
                mma8(s[nt], aq, b0, b1);
            }
        }

        // ---- online softmax + write P (tf32) to smem ----
        {
            float tl = -1e30f, th = -1e30f;
#pragma unroll
            for (int nt = 0; nt < 8; nt++) {
                tl = fmaxf(tl, fmaxf(s[nt][0], s[nt][1]));
                th = fmaxf(th, fmaxf(s[nt][2], s[nt][3]));
            }
            tl = fmaxf(tl, __shfl_xor_sync(0xffffffffu, tl, 1));
            tl = fmaxf(tl, __shfl_xor_sync(0xffffffffu, tl, 2));
            th = fmaxf(th, __shfl_xor_sync(0xffffffffu, th, 1));
            th = fmaxf(th, __shfl_xor_sync(0xffffffffu, th, 2));

            const float mlo = fmaxf(mrow[0], tl);
            const float mhi = fmaxf(mrow[1], th);
            const float alo = fex2(mrow[0] - mlo);
            const float ahi = fex2(mrow[1] - mhi);
            mrow[0] = mlo; mrow[1] = mhi;
            lrow[0] *= alo; lrow[1] *= ahi;
#pragma unroll
            for (int dt = 0; dt < 8; dt++) {
                o[dt][0] *= alo; o[dt][1] *= alo;
                o[dt][2] *= ahi; o[dt][3] *= ahi;
            }
#pragma unroll
            for (int nt = 0; nt < 8; nt++) {
                const float p0 = fex2(s[nt][0] - mlo);
                const float p1 = fex2(s[nt][1] - mlo);
                const float p2 = fex2(s[nt][2] - mhi);
                const float p3 = fex2(s[nt][3] - mhi);
                lrow[0] += p0 + p1;
                lrow[1] += p2 + p3;
                const int kc = nt * 8 + 2 * t;
                Ps[qr * ASTR + kc]           = f2tf(p0);
                Ps[qr * ASTR + kc + 1]       = f2tf(p1);
                Ps[(qr + 8) * ASTR + kc]     = f2tf(p2);
                Ps[(qr + 8) * ASTR + kc + 1] = f2tf(p3);
            }
        }
        __syncwarp();

        // ---- O += P @ V ----
#pragma unroll
        for (int ks = 0; ks < 8; ks++) {
            const int kk = ks * 8;
            uint32_t ap[4];
            ap[0] = Ps[qr * ASTR + kk + t];
            ap[1] = Ps[(qr + 8) * ASTR + kk + t];
            ap[2] = Ps[qr * ASTR + kk + t + 4];
            ap[3] = Ps[(qr + 8) * ASTR + kk + t + 4];
#pragma unroll
            for (int nt = 0; nt < 8; nt++) {
                const uint32_t b0 = Vs[(kk + t) * ASTR + nt * 8 + g];
                const uint32_t b1 = Vs[(kk + t + 4) * ASTR + nt * 8 + g];
                mma8(o[nt], ap, b0, b1);
            }
        }
    }

    // finalize: reduce row sums across the 4-lane group, normalize, store
    const int b = bh >> 4, h = bh & 15;
    float l0 = lrow[0], l1 = lrow[1];
    l0 += __shfl_xor_sync(0xffffffffu, l0, 1);
    l0 += __shfl_xor_sync(0xffffffffu, l0, 2);
    l1 += __shfl_xor_sync(0xffffffffu, l1, 1);
    l1 += __shfl_xor_sync(0xffffffffu, l1, 2);
    const float i0 = 1.f / l0, i1 = 1.f / l1;
    const int qg = qb + warp * 16 + g;
#pragma unroll
    for (int nt = 0; nt < 8; nt++) {
        const int col = h * 64 + nt * 8 + 2 * t;
        float2 w0 = make_float2(o[nt][0] * i0, o[nt][1] * i0);
        float2 w1 = make_float2(o[nt][2] * i1, o[nt][3] * i1);
        *(float2*)(att + (size_t)(b * NSEQ + qg) * CDIM + col) = w0;
        *(float2*)(att + (size_t)(b * NSEQ + qg + 8) * CDIM + col) = w1;
    }
}

// ---------------------------------------------------------------------------

extern "C" void kernel_launch(void* const* d_in, const int* in_sizes, int n_in,
                              void* d_out, int out_size)
{
    const float* x  = (const float*)d_in[0];
    const float* Wq = (const float*)d_in[1];
    const float* bq = (const float*)d_in[2];
    const float* Wk = (const float*)d_in[3];
    const float* bk = (const float*)d_in[4];
    const float* Wv = (const float*)d_in[5];
    const float* bv = (const float*)d_in[6];
    const float* Wo = (const float*)d_in[7];
    const float* bo = (const float*)d_in[8];
    float* out = (float*)d_out;

    float *Qp, *Kp, *Vp, *Ap;
    cudaGetSymbolAddress((void**)&Qp, g_Q);
    cudaGetSymbolAddress((void**)&Kp, g_K);
    cudaGetSymbolAddress((void**)&Vp, g_V);
    cudaGetSymbolAddress((void**)&Ap, g_att);

    const dim3 ggrid(CDIM / 128, MTOT / 128);  // (8, 64)

    gemm_tf32<1><<<ggrid, 256>>>(x, Wq, bq, Qp);
    gemm_tf32<1><<<ggrid, 256>>>(x, Wk, bk, Kp);
    gemm_tf32<1><<<ggrid, 256>>>(x, Wv, bv, Vp);

    const int att_smem = (128 * ASTR + 64 * ASTR + 64 * ASTR + 128 * ASTR) * 4;
    cudaFuncSetAttribute(attn_tf32,
                         cudaFuncAttributeMaxDynamicSharedMemorySize, att_smem);
    attn_tf32<<<dim3(NSEQ / 128, BATCH * NHEADS), 256, att_smem>>>(Qp, Kp, Vp, Ap);

    gemm_tf32<0><<<ggrid, 256>>>(Ap, Wo, bo, out);
}

// round 5
// speedup vs baseline: 2.7359x; 1.1030x over previous
#include <cuda_runtime.h>
#include <math.h>
#include <stdint.h>

#define BATCH   4
#define NSEQ    2048
#define CDIM    1024
#define NHEADS  16
#define HDIM    64
#define MTOT    (BATCH * NSEQ)   // 8192

// Scratch (allocation-free rule: __device__ globals)
__device__ float g_Q[BATCH * NHEADS * NSEQ * HDIM];   // [B,H,N,D]
__device__ float g_K[BATCH * NHEADS * NSEQ * HDIM];
__device__ float g_V[BATCH * NHEADS * NSEQ * HDIM];
__device__ float g_att[MTOT * CDIM];                  // [B,N,C]

__device__ __forceinline__ uint32_t f2tf(float f) {
    uint32_t u;
    asm("cvt.rna.tf32.f32 %0, %1;" : "=r"(u) : "f"(f));
    return u;
}
__device__ __forceinline__ float fex2(float x) {
    float r;
    asm("ex2.approx.f32 %0, %1;" : "=f"(r) : "f"(x));
    return r;
}
// pack two fp32 into f16x2: lo in low half, hi in high half
__device__ __forceinline__ uint32_t pack_f16(float lo, float hi) {
    uint32_t r;
    asm("cvt.rn.f16x2.f32 %0, %1, %2;" : "=r"(r) : "f"(hi), "f"(lo));
    return r;
}
__device__ __forceinline__ void mma8(float* c, const uint32_t* a,
                                     uint32_t b0, uint32_t b1) {
    asm volatile(
        "mma.sync.aligned.m16n8k8.row.col.f32.tf32.tf32.f32 "
        "{%0,%1,%2,%3}, {%4,%5,%6,%7}, {%8,%9}, {%0,%1,%2,%3};"
        : "+f"(c[0]), "+f"(c[1]), "+f"(c[2]), "+f"(c[3])
        : "r"(a[0]), "r"(a[1]), "r"(a[2]), "r"(a[3]), "r"(b0), "r"(b1));
}
__device__ __forceinline__ void mma16h(float* c, const uint32_t* a,
                                       uint32_t b0, uint32_t b1) {
    asm volatile(
        "mma.sync.aligned.m16n8k16.row.col.f32.f16.f16.f32 "
        "{%0,%1,%2,%3}, {%4,%5,%6,%7}, {%8,%9}, {%0,%1,%2,%3};"
        : "+f"(c[0]), "+f"(c[1]), "+f"(c[2]), "+f"(c[3])
        : "r"(a[0]), "r"(a[1]), "r"(a[2]), "r"(a[3]), "r"(b0), "r"(b1));
}
__device__ __forceinline__ void ldsm4t(uint32_t& r0, uint32_t& r1,
                                       uint32_t& r2, uint32_t& r3,
                                       uint32_t addr) {
    asm volatile(
        "ldmatrix.sync.aligned.m8n8.x4.trans.shared.b16 {%0,%1,%2,%3}, [%4];"
        : "=r"(r0), "=r"(r1), "=r"(r2), "=r"(r3) : "r"(addr));
}

// ---------------------------------------------------------------------------
// TF32 tensor-core GEMM: out = A[M,1024] @ W[1024,1024] + bias
// 128x128x16 block tile, 256 threads (8 warps), warp tile 64x32.
// Double-buffered smem; one __syncthreads per k-tile.
// MODE 0: row-major [M,N]   MODE 1: scatter to [B,H,N,D]
// ---------------------------------------------------------------------------
#define GS 136

template <int MODE>
__global__ __launch_bounds__(256, 2)
void gemm_tf32(const float* __restrict__ A, const float* __restrict__ W,
               const float* __restrict__ bias, float* __restrict__ out)
{
    __shared__ uint32_t As[2][16 * GS];
    __shared__ uint32_t Bs[2][16 * GS];

    const int tid = threadIdx.x, lane = tid & 31, warp = tid >> 5;
    const int g = lane >> 2, t = lane & 3;
    const int wm = (warp & 1) * 64, wn = (warp >> 1) * 32;
    const int row0 = blockIdx.y * 128, col0 = blockIdx.x * 128;

    const int am = tid & 127, ak = (tid >> 7) * 8;
    const int bk = tid >> 4,  bn = (tid & 15) * 8;
    const float* Ag = A + (size_t)(row0 + am) * CDIM + ak;
    const float* Bg = W + (size_t)bk * CDIM + col0 + bn;

    float acc[4][4][4];
#pragma unroll
    for (int i = 0; i < 4; i++)
#pragma unroll
        for (int j = 0; j < 4; j++)
#pragma unroll
            for (int v = 0; v < 4; v++) acc[i][j][v] = 0.f;

    float4 ra0 = *(const float4*)(Ag);
    float4 ra1 = *(const float4*)(Ag + 4);
    float4 rb0 = *(const float4*)(Bg);
    float4 rb1 = *(const float4*)(Bg + 4);
    As[0][(ak + 0) * GS + am] = f2tf(ra0.x);
    As[0][(ak + 1) * GS + am] = f2tf(ra0.y);
    As[0][(ak + 2) * GS + am] = f2tf(ra0.z);
    As[0][(ak + 3) * GS + am] = f2tf(ra0.w);
    As[0][(ak + 4) * GS + am] = f2tf(ra1.x);
    As[0][(ak + 5) * GS + am] = f2tf(ra1.y);
    As[0][(ak + 6) * GS + am] = f2tf(ra1.z);
    As[0][(ak + 7) * GS + am] = f2tf(ra1.w);
    *(uint4*)&Bs[0][bk * GS + bn] =
        make_uint4(f2tf(rb0.x), f2tf(rb0.y), f2tf(rb0.z), f2tf(rb0.w));
    *(uint4*)&Bs[0][bk * GS + bn + 4] =
        make_uint4(f2tf(rb1.x), f2tf(rb1.y), f2tf(rb1.z), f2tf(rb1.w));
    __syncthreads();

    int buf = 0;
    for (int k0 = 0; k0 < CDIM; k0 += 16) {
        const bool more = (k0 + 16 < CDIM);
        if (more) {
            ra0 = *(const float4*)(Ag + k0 + 16);
            ra1 = *(const float4*)(Ag + k0 + 20);
            rb0 = *(const float4*)(Bg + (size_t)(k0 + 16) * CDIM);
            rb1 = *(const float4*)(Bg + (size_t)(k0 + 16) * CDIM + 4);
        }

        const uint32_t* Ab = As[buf];
        const uint32_t* Bb = Bs[buf];
#pragma unroll
        for (int ks = 0; ks < 2; ks++) {
            const int kb = ks * 8;
            uint32_t af[4][4];
#pragma unroll
            for (int mt = 0; mt < 4; mt++) {
                const int m = wm + mt * 16 + g;
                af[mt][0] = Ab[(kb + t) * GS + m];
                af[mt][1] = Ab[(kb + t) * GS + m + 8];
                af[mt][2] = Ab[(kb + t + 4) * GS + m];
                af[mt][3] = Ab[(kb + t + 4) * GS + m + 8];
            }
#pragma unroll
            for (int nt = 0; nt < 4; nt++) {
                const int n = wn + nt * 8 + g;
                const uint32_t b0 = Bb[(kb + t) * GS + n];
                const uint32_t b1 = Bb[(kb + t + 4) * GS + n];
#pragma unroll
                for (int mt = 0; mt < 4; mt++) mma8(acc[mt][nt], af[mt], b0, b1);
            }
        }

        if (more) {
            uint32_t* An = As[buf ^ 1];
            uint32_t* Bn = Bs[buf ^ 1];
            An[(ak + 0) * GS + am] = f2tf(ra0.x);
            An[(ak + 1) * GS + am] = f2tf(ra0.y);
            An[(ak + 2) * GS + am] = f2tf(ra0.z);
            An[(ak + 3) * GS + am] = f2tf(ra0.w);
            An[(ak + 4) * GS + am] = f2tf(ra1.x);
            An[(ak + 5) * GS + am] = f2tf(ra1.y);
            An[(ak + 6) * GS + am] = f2tf(ra1.z);
            An[(ak + 7) * GS + am] = f2tf(ra1.w);
            *(uint4*)&Bn[bk * GS + bn] =
                make_uint4(f2tf(rb0.x), f2tf(rb0.y), f2tf(rb0.z), f2tf(rb0.w));
            *(uint4*)&Bn[bk * GS + bn + 4] =
                make_uint4(f2tf(rb1.x), f2tf(rb1.y), f2tf(rb1.z), f2tf(rb1.w));
            __syncthreads();
            buf ^= 1;
        }
    }

#pragma unroll
    for (int mt = 0; mt < 4; mt++) {
        const int r = row0 + wm + mt * 16 + g;
#pragma unroll
        for (int nt = 0; nt < 4; nt++) {
            const int c = col0 + wn + nt * 8 + 2 * t;
            const float bx = bias[c], by = bias[c + 1];
            float2 v0 = make_float2(acc[mt][nt][0] + bx, acc[mt][nt][1] + by);
            float2 v1 = make_float2(acc[mt][nt][2] + bx, acc[mt][nt][3] + by);
            if (MODE == 0) {
                *(float2*)(out + (size_t)r * CDIM + c) = v0;
                *(float2*)(out + (size_t)(r + 8) * CDIM + c) = v1;
            } else {
                const int h = c >> 6, d = c & 63;
                const int bi = r >> 11, ni = r & (NSEQ - 1);
                *(float2*)(out + ((size_t)(bi * NHEADS + h) * NSEQ + ni) * HDIM + d) = v0;
                *(float2*)(out + ((size_t)(bi * NHEADS + h) * NSEQ + ni + 8) * HDIM + d) = v1;
            }
        }
    }
}

// ---------------------------------------------------------------------------
// Flash attention v4:
//  - S = QK^T in tf32 mma (K frags via LDS, conflict-free stride 72)
//  - P stays in REGISTERS packed to fp16 (S C-layout == f16 A-layout)
//  - PV in fp16 m16n8k16 mma (fp32 accum), V staged as fp16,
//    B-frags via ldmatrix.x4.trans
//  - smem 64.5 KB -> 2 CTAs/SM
// ---------------------------------------------------------------------------
#define ASTR 72     // tf32 smem row stride (words)
#define VSTRW 36    // V fp16 smem row stride in uint32 words (= 72 halves)

__global__ __launch_bounds__(256, 2)
void attn_tc(const float* __restrict__ Qg, const float* __restrict__ Kg,
             const float* __restrict__ Vg, float* __restrict__ att)
{
    extern __shared__ uint32_t sm[];
    uint32_t* Qs = sm;                       // [128][72] tf32
    uint32_t* Ks = Qs + 128 * ASTR;          // [64][72]  tf32 (key-major)
    uint32_t* Vs = Ks + 64 * ASTR;           // [64][36w] fp16 (key-major)

    const int tid = threadIdx.x, lane = tid & 31, warp = tid >> 5;
    const int g = lane >> 2, t = lane & 3;
    const int bh = blockIdx.y;
    const int qb = blockIdx.x * 128;

    const float* Q = Qg + (size_t)bh * NSEQ * HDIM;
    const float* K = Kg + (size_t)bh * NSEQ * HDIM;
    const float* V = Vg + (size_t)bh * NSEQ * HDIM;

    const uint32_t vbase = (uint32_t)__cvta_generic_to_shared(Vs);

    // stage Q once: scaled by (1/sqrt(D)) * log2(e), tf32
    const float qscale = 0.125f * 1.4426950408889634f;
    for (int idx = tid; idx < 128 * 16; idx += 256) {
        const int m = idx >> 4, d4 = (idx & 15) * 4;
        float4 v = *(const float4*)(Q + (size_t)(qb + m) * HDIM + d4);
        *(uint4*)&Qs[m * ASTR + d4] =
            make_uint4(f2tf(v.x * qscale), f2tf(v.y * qscale),
                       f2tf(v.z * qscale), f2tf(v.w * qscale));
    }

    float o[8][4];
#pragma unroll
    for (int b = 0; b < 8; b++)
#pragma unroll
        for (int c = 0; c < 4; c++) o[b][c] = 0.f;
    float mrow[2] = {-1e30f, -1e30f};
    float lrow[2] = {0.f, 0.f};

    const int qr = warp * 16 + g;

    for (int kt = 0; kt < NSEQ; kt += 64) {
        __syncthreads();   // previous tile fully consumed
        // stage K (tf32) and V (fp16)
        for (int idx = tid; idx < 64 * 16; idx += 256) {
            const int key = idx >> 4, c4 = idx & 15;
            float4 kv = *(const float4*)(K + (size_t)(kt + key) * HDIM + c4 * 4);
            float4 vv = *(const float4*)(V + (size_t)(kt + key) * HDIM + c4 * 4);
            *(uint4*)&Ks[key * ASTR + c4 * 4] =
                make_uint4(f2tf(kv.x), f2tf(kv.y), f2tf(kv.z), f2tf(kv.w));
            uint32_t* vrow = Vs + key * VSTRW + c4 * 2;
            vrow[0] = pack_f16(vv.x, vv.y);
            vrow[1] = pack_f16(vv.z, vv.w);
        }
        __syncthreads();

        // ---- S = Q @ K^T (tf32, scaled, base-2) ----
        float s[8][4];
#pragma unroll
        for (int b = 0; b < 8; b++)
#pragma unroll
            for (int c = 0; c < 4; c++) s[b][c] = 0.f;

#pragma unroll
        for (int ks = 0; ks < 8; ks++) {
            const int kd = ks * 8;
            uint32_t aq[4];
            aq[0] = Qs[qr * ASTR + kd + t];
            aq[1] = Qs[(qr + 8) * ASTR + kd + t];
            aq[2] = Qs[qr * ASTR + kd + t + 4];
            aq[3] = Qs[(qr + 8) * ASTR + kd + t + 4];
#pragma unroll
            for (int nt = 0; nt < 8; nt++) {
                const uint32_t b0 = Ks[(nt * 8 + g) * ASTR + kd + t];
                const uint32_t b1 = Ks[(nt * 8 + g) * ASTR + kd + t + 4];
                mma8(s[nt], aq, b0, b1);
            }
        }

        // ---- online softmax; P packed to fp16 in registers ----
        uint32_t pk[8][2];
        {
            float tl = -1e30f, th = -1e30f;
#pragma unroll
            for (int nt = 0; nt < 8; nt++) {
                tl = fmaxf(tl, fmaxf(s[nt][0], s[nt][1]));
                th = fmaxf(th, fmaxf(s[nt][2], s[nt][3]));
            }
            tl = fmaxf(tl, __shfl_xor_sync(0xffffffffu, tl, 1));
            tl = fmaxf(tl, __shfl_xor_sync(0xffffffffu, tl, 2));
            th = fmaxf(th, __shfl_xor_sync(0xffffffffu, th, 1));
            th = fmaxf(th, __shfl_xor_sync(0xffffffffu, th, 2));

            const float mlo = fmaxf(mrow[0], tl);
            const float mhi = fmaxf(mrow[1], th);
            const float alo = fex2(mrow[0] - mlo);
            const float ahi = fex2(mrow[1] - mhi);
            mrow[0] = mlo; mrow[1] = mhi;
            lrow[0] *= alo; lrow[1] *= ahi;
#pragma unroll
            for (int dt = 0; dt < 8; dt++) {
                o[dt][0] *= alo; o[dt][1] *= alo;
                o[dt][2] *= ahi; o[dt][3] *= ahi;
            }
#pragma unroll
            for (int nt = 0; nt < 8; nt++) {
                const float p0 = fex2(s[nt][0] - mlo);
                const float p1 = fex2(s[nt][1] - mlo);
                const float p2 = fex2(s[nt][2] - mhi);
                const float p3 = fex2(s[nt][3] - mhi);
                lrow[0] += p0 + p1;
                lrow[1] += p2 + p3;
                pk[nt][0] = pack_f16(p0, p1);   // row g,   cols 2t,2t+1
                pk[nt][1] = pack_f16(p2, p3);   // row g+8, cols 2t,2t+1
            }
        }

        // ---- O += P @ V  (fp16 m16n8k16; V frags via ldmatrix.trans) ----
#pragma unroll
        for (int kc = 0; kc < 4; kc++) {       // 16-key chunks
            uint32_t ap[4];
            ap[0] = pk[2 * kc][0];
            ap[1] = pk[2 * kc][1];
            ap[2] = pk[2 * kc + 1][0];
            ap[3] = pk[2 * kc + 1][1];
#pragma unroll
            for (int j = 0; j < 4; j++) {      // dim pairs of 16
                uint32_t r0, r1, r2, r3;
                const uint32_t addr = vbase +
                    ((kc * 16 + (lane & 15)) * VSTRW + j * 8 + 4 * (lane >> 4)) * 4;
                ldsm4t(r0, r1, r2, r3, addr);
                mma16h(o[2 * j],     ap, r0, r1);
                mma16h(o[2 * j + 1], ap, r2, r3);
            }
        }
    }

    // finalize: reduce row sums across the 4-lane group, normalize, store
    const int b = bh >> 4, h = bh & 15;
    float l0 = lrow[0], l1 = lrow[1];
    l0 += __shfl_xor_sync(0xffffffffu, l0, 1);
    l0 += __shfl_xor_sync(0xffffffffu, l0, 2);
    l1 += __shfl_xor_sync(0xffffffffu, l1, 1);
    l1 += __shfl_xor_sync(0xffffffffu, l1, 2);
    const float i0 = 1.f / l0, i1 = 1.f / l1;
    const int qg = qb + warp * 16 + g;
#pragma unroll
    for (int nt = 0; nt < 8; nt++) {
        const int col = h * 64 + nt * 8 + 2 * t;
        float2 w0 = make_float2(o[nt][0] * i0, o[nt][1] * i0);
        float2 w1 = make_float2(o[nt][2] * i1, o[nt][3] * i1);
        *(float2*)(att + (size_t)(b * NSEQ + qg) * CDIM + col) = w0;
        *(float2*)(att + (size_t)(b * NSEQ + qg + 8) * CDIM + col) = w1;
    }
}

// ---------------------------------------------------------------------------

extern "C" void kernel_launch(void* const* d_in, const int* in_sizes, int n_in,
                              void* d_out, int out_size)
{
    const float* x  = (const float*)d_in[0];
    const float* Wq = (const float*)d_in[1];
    const float* bq = (const float*)d_in[2];
    const float* Wk = (const float*)d_in[3];
    const float* bk = (const float*)d_in[4];
    const float* Wv = (const float*)d_in[5];
    const float* bv = (const float*)d_in[6];
    const float* Wo = (const float*)d_in[7];
    const float* bo = (const float*)d_in[8];
    float* out = (float*)d_out;

    float *Qp, *Kp, *Vp, *Ap;
    cudaGetSymbolAddress((void**)&Qp, g_Q);
    cudaGetSymbolAddress((void**)&Kp, g_K);
    cudaGetSymbolAddress((void**)&Vp, g_V);
    cudaGetSymbolAddress((void**)&Ap, g_att);

    const dim3 ggrid(CDIM / 128, MTOT / 128);  // (8, 64)

    gemm_tf32<1><<<ggrid, 256>>>(x, Wq, bq, Qp);
    gemm_tf32<1><<<ggrid, 256>>>(x, Wk, bk, Kp);
    gemm_tf32<1><<<ggrid, 256>>>(x, Wv, bv, Vp);

    const int att_smem = (128 * ASTR + 64 * ASTR + 64 * VSTRW) * 4;
    cudaFuncSetAttribute(attn_tc,
                         cudaFuncAttributeMaxDynamicSharedMemorySize, att_smem);
    attn_tc<<<dim3(NSEQ / 128, BATCH * NHEADS), 256, att_smem>>>(Qp, Kp, Vp, Ap);

    gemm_tf32<0><<<ggrid, 256>>>(Ap, Wo, bo, out);
}

// round 6
// speedup vs baseline: 4.2532x; 1.5546x over previous
#include <cuda_runtime.h>
#include <math.h>
#include <stdint.h>

#define BATCH   4
#define NSEQ    2048
#define CDIM    1024
#define NHEADS  16
#define HDIM    64
#define MTOT    (BATCH * NSEQ)   // 8192

// Scratch (allocation-free rule: __device__ globals)
__device__ float g_Q[BATCH * NHEADS * NSEQ * HDIM];   // [B,H,N,D]
__device__ float g_K[BATCH * NHEADS * NSEQ * HDIM];
__device__ float g_V[BATCH * NHEADS * NSEQ * HDIM];
__device__ float g_att[MTOT * CDIM];                  // [B,N,C]

__device__ __forceinline__ float fex2(float x) {
    float r;
    asm("ex2.approx.f32 %0, %1;" : "=f"(r) : "f"(x));
    return r;
}
// pack two fp32 into f16x2: lo in low half, hi in high half
__device__ __forceinline__ uint32_t pack_f16(float lo, float hi) {
    uint32_t r;
    asm("cvt.rn.f16x2.f32 %0, %1, %2;" : "=r"(r) : "f"(hi), "f"(lo));
    return r;
}
__device__ __forceinline__ void mma16h(float* c, const uint32_t* a,
                                       uint32_t b0, uint32_t b1) {
    asm volatile(
        "mma.sync.aligned.m16n8k16.row.col.f32.f16.f16.f32 "
        "{%0,%1,%2,%3}, {%4,%5,%6,%7}, {%8,%9}, {%0,%1,%2,%3};"
        : "+f"(c[0]), "+f"(c[1]), "+f"(c[2]), "+f"(c[3])
        : "r"(a[0]), "r"(a[1]), "r"(a[2]), "r"(a[3]), "r"(b0), "r"(b1));
}
__device__ __forceinline__ void ldsm4(uint32_t& r0, uint32_t& r1,
                                      uint32_t& r2, uint32_t& r3,
                                      uint32_t addr) {
    asm volatile(
        "ldmatrix.sync.aligned.m8n8.x4.shared.b16 {%0,%1,%2,%3}, [%4];"
        : "=r"(r0), "=r"(r1), "=r"(r2), "=r"(r3) : "r"(addr));
}
__device__ __forceinline__ void ldsm4t(uint32_t& r0, uint32_t& r1,
                                       uint32_t& r2, uint32_t& r3,
                                       uint32_t addr) {
    asm volatile(
        "ldmatrix.sync.aligned.m8n8.x4.trans.shared.b16 {%0,%1,%2,%3}, [%4];"
        : "=r"(r0), "=r"(r1), "=r"(r2), "=r"(r3) : "r"(addr));
}

// ---------------------------------------------------------------------------
// FP16 tensor-core GEMM: out = A[M,1024] @ W[1024,1024] + bias  (fp32 accum)
// 128x128x16 block tile, 256 threads (8 warps), warp tile 64x32.
// A smem [m][k] stride 24 halves; B smem [k][n] stride 136 halves.
// A-frags: ldmatrix.x4; W-frags: ldmatrix.x4.trans. Double-buffered.
// MODE 0: row-major [M,N]   MODE 1: scatter to [B,H,N,D]
// ---------------------------------------------------------------------------
#define AST 24    // A smem row stride (halves): 48B = 12 banks -> conflict-free
#define BST 136   // B smem row stride (halves): 272B = 68 banks === 4 mod 32

template <int MODE>
__global__ __launch_bounds__(256, 2)
void gemm_h(const float* __restrict__ A, const float* __restrict__ W,
            const float* __restrict__ bias, float* __restrict__ out)
{
    __shared__ uint16_t Ah[2][128 * AST];
    __shared__ uint16_t Bh[2][16 * BST];

    const int tid = threadIdx.x, lane = tid & 31, warp = tid >> 5;
    const int g = lane >> 2, t = lane & 3;
    const int wm = (warp & 1) * 64, wn = (warp >> 1) * 32;
    const int row0 = blockIdx.y * 128, col0 = blockIdx.x * 128;

    const int am = tid & 127, ak = (tid >> 7) * 8;
    const int bk = tid >> 4,  bn = (tid & 15) * 8;
    const float* Ag = A + (size_t)(row0 + am) * CDIM + ak;
    const float* Bg = W + (size_t)bk * CDIM + col0 + bn;

    const uint32_t abase0 = (uint32_t)__cvta_generic_to_shared(Ah[0]);
    const uint32_t abase1 = (uint32_t)__cvta_generic_to_shared(Ah[1]);
    const uint32_t bbase0 = (uint32_t)__cvta_generic_to_shared(Bh[0]);
    const uint32_t bbase1 = (uint32_t)__cvta_generic_to_shared(Bh[1]);

    // ldmatrix source offsets (bytes)
    const uint32_t a_frag_off =
        (uint32_t)(((lane & 7) + 8 * ((lane >> 3) & 1)) * AST + (lane >> 4) * 8) * 2;
    const uint32_t b_frag_off =
        (uint32_t)((lane & 15) * BST + 8 * (lane >> 4)) * 2;

    float acc[4][4][4];
#pragma unroll
    for (int i = 0; i < 4; i++)
#pragma unroll
        for (int j = 0; j < 4; j++)
#pragma unroll
            for (int v = 0; v < 4; v++) acc[i][j][v] = 0.f;

    // prologue: load + stage tile 0
    float4 ra0 = *(const float4*)(Ag);
    float4 ra1 = *(const float4*)(Ag + 4);
    float4 rb0 = *(const float4*)(Bg);
    float4 rb1 = *(const float4*)(Bg + 4);
    *(uint4*)&Ah[0][am * AST + ak] =
        make_uint4(pack_f16(ra0.x, ra0.y), pack_f16(ra0.z, ra0.w),
                   pack_f16(ra1.x, ra1.y), pack_f16(ra1.z, ra1.w));
    *(uint4*)&Bh[0][bk * BST + bn] =
        make_uint4(pack_f16(rb0.x, rb0.y), pack_f16(rb0.z, rb0.w),
                   pack_f16(rb1.x, rb1.y), pack_f16(rb1.z, rb1.w));
    __syncthreads();

    int buf = 0;
    for (int k0 = 0; k0 < CDIM; k0 += 16) {
        const bool more = (k0 + 16 < CDIM);
        if (more) {
            ra0 = *(const float4*)(Ag + k0 + 16);
            ra1 = *(const float4*)(Ag + k0 + 20);
            rb0 = *(const float4*)(Bg + (size_t)(k0 + 16) * CDIM);
            rb1 = *(const float4*)(Bg + (size_t)(k0 + 16) * CDIM + 4);
        }

        const uint32_t abase = buf ? abase1 : abase0;
        const uint32_t bbase = buf ? bbase1 : bbase0;

        uint32_t af[4][4];
#pragma unroll
        for (int mt = 0; mt < 4; mt++) {
            const uint32_t addr = abase + a_frag_off +
                (uint32_t)((wm + mt * 16) * AST) * 2;
            ldsm4(af[mt][0], af[mt][1], af[mt][2], af[mt][3], addr);
        }
#pragma unroll
        for (int j = 0; j < 2; j++) {
            uint32_t r0, r1, r2, r3;
            const uint32_t addr = bbase + b_frag_off +
                (uint32_t)(wn + j * 16) * 2;
            ldsm4t(r0, r1, r2, r3, addr);
#pragma unroll
            for (int mt = 0; mt < 4; mt++) {
                mma16h(acc[mt][2 * j],     af[mt], r0, r1);
                mma16h(acc[mt][2 * j + 1], af[mt], r2, r3);
            }
        }

        if (more) {
            *(uint4*)&Ah[buf ^ 1][am * AST + ak] =
                make_uint4(pack_f16(ra0.x, ra0.y), pack_f16(ra0.z, ra0.w),
                           pack_f16(ra1.x, ra1.y), pack_f16(ra1.z, ra1.w));
            *(uint4*)&Bh[buf ^ 1][bk * BST + bn] =
                make_uint4(pack_f16(rb0.x, rb0.y), pack_f16(rb0.z, rb0.w),
                           pack_f16(rb1.x, rb1.y), pack_f16(rb1.z, rb1.w));
            __syncthreads();
            buf ^= 1;
        }
    }

    // epilogue: bias + store (fp32 accum)
#pragma unroll
    for (int mt = 0; mt < 4; mt++) {
        const int r = row0 + wm + mt * 16 + g;
#pragma unroll
        for (int nt = 0; nt < 4; nt++) {
            const int c = col0 + wn + nt * 8 + 2 * t;
            const float bx = bias[c], by = bias[c + 1];
            float2 v0 = make_float2(acc[mt][nt][0] + bx, acc[mt][nt][1] + by);
            float2 v1 = make_float2(acc[mt][nt][2] + bx, acc[mt][nt][3] + by);
            if (MODE == 0) {
                *(float2*)(out + (size_t)r * CDIM + c) = v0;
                *(float2*)(out + (size_t)(r + 8) * CDIM + c) = v1;
            } else {
                const int h = c >> 6, d = c & 63;
                const int bi = r >> 11, ni = r & (NSEQ - 1);
                *(float2*)(out + ((size_t)(bi * NHEADS + h) * NSEQ + ni) * HDIM + d) = v0;
                *(float2*)(out + ((size_t)(bi * NHEADS + h) * NSEQ + ni + 8) * HDIM + d) = v1;
            }
        }
    }
}

// ---------------------------------------------------------------------------
// Flash attention v5 (all fp16 operands, fp32 accum):
//  - Q staged fp16 once, fragments hoisted into 16 REGISTERS (no Q LDS in loop)
//  - S = QK^T fp16 m16n8k16; K-frags via ldmatrix.x4 (non-trans)
//  - P packed fp16 in registers; PV fp16 m16n8k16, V-frags ldmatrix.x4.trans
//  - smem 36.9 KB; strides 72 halves (144B === 4 banks mod 32, 16B-multiple)
// ---------------------------------------------------------------------------
#define QSTR 72   // halves

__global__ __launch_bounds__(256, 2)
void attn_h(const float* __restrict__ Qg, const float* __restrict__ Kg,
            const float* __restrict__ Vg, float* __restrict__ att)
{
    extern __shared__ uint16_t smh[];
    uint16_t* Qh = smh;                    // [128][72]
    uint16_t* Kh = Qh + 128 * QSTR;        // [64][72]  (key-major)
    uint16_t* Vh = Kh + 64 * QSTR;         // [64][72]  (key-major)

    const int tid = threadIdx.x, lane = tid & 31, warp = tid >> 5;
    const int g = lane >> 2, t = lane & 3;
    const int bh = blockIdx.y;
    const int qb = blockIdx.x * 128;

    const float* Q = Qg + (size_t)bh * NSEQ * HDIM;
    const float* K = Kg + (size_t)bh * NSEQ * HDIM;
    const float* V = Vg + (size_t)bh * NSEQ * HDIM;

    const uint32_t qbase = (uint32_t)__cvta_generic_to_shared(Qh);
    const uint32_t kbase = (uint32_t)__cvta_generic_to_shared(Kh);
    const uint32_t vbase = (uint32_t)__cvta_generic_to_shared(Vh);

    // common ldmatrix lane-offset pieces (bytes)
    const uint32_t afrag_row = (lane & 7) + 8 * ((lane >> 3) & 1);
    const uint32_t afrag_col = (lane >> 4) * 8;           // halves
    const uint32_t bfrag_row = lane & 15;
    const uint32_t bfrag_col = 8 * (lane >> 4);           // halves

    // stage Q once: scaled by (1/sqrt(D)) * log2(e), fp16
    const float qscale = 0.125f * 1.4426950408889634f;
    for (int idx = tid; idx < 128 * 16; idx += 256) {
        const int m = idx >> 4, c4 = idx & 15;
        float4 v = *(const float4*)(Q + (size_t)(qb + m) * HDIM + c4 * 4);
        uint32_t* dst = (uint32_t*)&Qh[m * QSTR + c4 * 4];
        dst[0] = pack_f16(v.x * qscale, v.y * qscale);
        dst[1] = pack_f16(v.z * qscale, v.w * qscale);
    }
    __syncthreads();

    // hoist Q fragments: 4 d16-chunks x 4 regs, invariant over the k-loop
    uint32_t aq[4][4];
#pragma unroll
    for (int dc = 0; dc < 4; dc++) {
        const uint32_t addr = qbase +
            (uint32_t)((warp * 16 + afrag_row) * QSTR + dc * 16 + afrag_col) * 2;
        ldsm4(aq[dc][0], aq[dc][1], aq[dc][2], aq[dc][3], addr);
    }

    float o[8][4];
#pragma unroll
    for (int b = 0; b < 8; b++)
#pragma unroll
        for (int c = 0; c < 4; c++) o[b][c] = 0.f;
    float mrow[2] = {-1e30f, -1e30f};
    float lrow[2] = {0.f, 0.f};

    for (int kt = 0; kt < NSEQ; kt += 64) {
        __syncthreads();   // previous tile fully consumed
        // stage K,V (fp16)
        for (int idx = tid; idx < 64 * 16; idx += 256) {
            const int key = idx >> 4, c4 = idx & 15;
            float4 kv = *(const float4*)(K + (size_t)(kt + key) * HDIM + c4 * 4);
            float4 vv = *(const float4*)(V + (size_t)(kt + key) * HDIM + c4 * 4);
            uint32_t* kd = (uint32_t*)&Kh[key * QSTR + c4 * 4];
            kd[0] = pack_f16(kv.x, kv.y);
            kd[1] = pack_f16(kv.z, kv.w);
            uint32_t* vd = (uint32_t*)&Vh[key * QSTR + c4 * 4];
            vd[0] = pack_f16(vv.x, vv.y);
            vd[1] = pack_f16(vv.z, vv.w);
        }
        __syncthreads();

        // ---- S = Q @ K^T (fp16 mma, K-frags via ldmatrix non-trans) ----
        float s[8][4];
#pragma unroll
        for (int b = 0; b < 8; b++)
#pragma unroll
            for (int c = 0; c < 4; c++) s[b][c] = 0.f;

#pragma unroll
        for (int dc = 0; dc < 4; dc++) {
#pragma unroll
            for (int kp = 0; kp < 4; kp++) {   // 16-key groups
                uint32_t r0, r1, r2, r3;
                const uint32_t addr = kbase +
                    (uint32_t)((kp * 16 + bfrag_row) * QSTR + dc * 16 + bfrag_col) * 2;
                ldsm4(r0, r1, r2, r3, addr);
                // r0/r2 = keys kp*16..+7 (d lo/hi), r1/r3 = keys +8..+15
                mma16h(s[2 * kp],     aq[dc], r0, r2);
                mma16h(s[2 * kp + 1], aq[dc], r1, r3);
            }
        }

        // ---- online softmax; P packed to fp16 in registers ----
        uint32_t pk[8][2];
        {
            float tl = -1e30f, th = -1e30f;
#pragma unroll
            for (int nt = 0; nt < 8; nt++) {
                tl = fmaxf(tl, fmaxf(s[nt][0], s[nt][1]));
                th = fmaxf(th, fmaxf(s[nt][2], s[nt][3]));
            }
            tl = fmaxf(tl, __shfl_xor_sync(0xffffffffu, tl, 1));
            tl = fmaxf(tl, __shfl_xor_sync(0xffffffffu, tl, 2));
            th = fmaxf(th, __shfl_xor_sync(0xffffffffu, th, 1));
            th = fmaxf(th, __shfl_xor_sync(0xffffffffu, th, 2));

            const float mlo = fmaxf(mrow[0], tl);
            const float mhi = fmaxf(mrow[1], th);
            const float alo = fex2(mrow[0] - mlo);
            const float ahi = fex2(mrow[1] - mhi);
            mrow[0] = mlo; mrow[1] = mhi;
            lrow[0] *= alo; lrow[1] *= ahi;
#pragma unroll
            for (int dt = 0; dt < 8; dt++) {
                o[dt][0] *= alo; o[dt][1] *= alo;
                o[dt][2] *= ahi; o[dt][3] *= ahi;
            }
#pragma unroll
            for (int nt = 0; nt < 8; nt++) {
                const float p0 = fex2(s[nt][0] - mlo);
                const float p1 = fex2(s[nt][1] - mlo);
                const float p2 = fex2(s[nt][2] - mhi);
                const float p3 = fex2(s[nt][3] - mhi);
                lrow[0] += p0 + p1;
                lrow[1] += p2 + p3;
                pk[nt][0] = pack_f16(p0, p1);   // row g,   cols 2t,2t+1
                pk[nt][1] = pack_f16(p2, p3);   // row g+8, cols 2t,2t+1
            }
        }

        // ---- O += P @ V  (fp16 mma; V-frags via ldmatrix.trans) ----
#pragma unroll
        for (int kc = 0; kc < 4; kc++) {       // 16-key chunks
            uint32_t ap[4];
            ap[0] = pk[2 * kc][0];
            ap[1] = pk[2 * kc][1];
            ap[2] = pk[2 * kc + 1][0];
            ap[3] = pk[2 * kc + 1][1];
#pragma unroll
            for (int j = 0; j < 4; j++) {      // dim chunks of 16
                uint32_t r0, r1, r2, r3;
                const uint32_t addr = vbase +
                    (uint32_t)((kc * 16 + bfrag_row) * QSTR + j * 16 + bfrag_col) * 2;
                ldsm4t(r0, r1, r2, r3, addr);
                mma16h(o[2 * j],     ap, r0, r1);
                mma16h(o[2 * j + 1], ap, r2, r3);
            }
        }
    }

    // finalize: reduce row sums across the 4-lane group, normalize, store
    const int b = bh >> 4, h = bh & 15;
    float l0 = lrow[0], l1 = lrow[1];
    l0 += __shfl_xor_sync(0xffffffffu, l0, 1);
    l0 += __shfl_xor_sync(0xffffffffu, l0, 2);
    l1 += __shfl_xor_sync(0xffffffffu, l1, 1);
    l1 += __shfl_xor_sync(0xffffffffu, l1, 2);
    const float i0 = 1.f / l0, i1 = 1.f / l1;
    const int qg = qb + warp * 16 + g;
#pragma unroll
    for (int nt = 0; nt < 8; nt++) {
        const int col = h * 64 + nt * 8 + 2 * t;
        float2 w0 = make_float2(o[nt][0] * i0, o[nt][1] * i0);
        float2 w1 = make_float2(o[nt][2] * i1, o[nt][3] * i1);
        *(float2*)(att + (size_t)(b * NSEQ + qg) * CDIM + col) = w0;
        *(float2*)(att + (size_t)(b * NSEQ + qg + 8) * CDIM + col) = w1;
    }
}

// ---------------------------------------------------------------------------

extern "C" void kernel_launch(void* const* d_in, const int* in_sizes, int n_in,
                              void* d_out, int out_size)
{
    const float* x  = (const float*)d_in[0];
    const float* Wq = (const float*)d_in[1];
    const float* bq = (const float*)d_in[2];
    const float* Wk = (const float*)d_in[3];
    const float* bk = (const float*)d_in[4];
    const float* Wv = (const float*)d_in[5];
    const float* bv = (const float*)d_in[6];
    const float* Wo = (const float*)d_in[7];
    const float* bo = (const float*)d_in[8];
    float* out = (float*)d_out;

    float *Qp, *Kp, *Vp, *Ap;
    cudaGetSymbolAddress((void**)&Qp, g_Q);
    cudaGetSymbolAddress((void**)&Kp, g_K);
    cudaGetSymbolAddress((void**)&Vp, g_V);
    cudaGetSymbolAddress((void**)&Ap, g_att);

    const dim3 ggrid(CDIM / 128, MTOT / 128);  // (8, 64)

    gemm_h<1><<<ggrid, 256>>>(x, Wq, bq, Qp);
    gemm_h<1><<<ggrid, 256>>>(x, Wk, bk, Kp);
    gemm_h<1><<<ggrid, 256>>>(x, Wv, bv, Vp);

    const int att_smem = (128 * QSTR + 64 * QSTR + 64 * QSTR) * 2;  // bytes
    cudaFuncSetAttribute(attn_h,
                         cudaFuncAttributeMaxDynamicSharedMemorySize, att_smem);
    attn_h<<<dim3(NSEQ / 128, BATCH * NHEADS), 256, att_smem>>>(Qp, Kp, Vp, Ap);

    gemm_h<0><<<ggrid, 256>>>(Ap, Wo, bo, out);
}

// round 7
// speedup vs baseline: 8.2008x; 1.9281x over previous
#include <cuda_runtime.h>
#include <cuda_fp16.h>
#include <math.h>
#include <stdint.h>

#define BATCH   4
#define NSEQ    2048
#define CDIM    1024
#define NHEADS  16
#define HDIM    64
#define MTOT    (BATCH * NSEQ)   // 8192

// Scratch (allocation-free rule: __device__ globals)
__device__ __half g_xh[MTOT * CDIM];                    // x in fp16
__device__ __half g_Wq[CDIM * CDIM];
__device__ __half g_Wk[CDIM * CDIM];
__device__ __half g_Wv[CDIM * CDIM];
__device__ __half g_Wo[CDIM * CDIM];
__device__ __half g_Q[BATCH * NHEADS * NSEQ * HDIM];    // [B,H,N,D] (pre-scaled)
__device__ __half g_K[BATCH * NHEADS * NSEQ * HDIM];
__device__ __half g_V[BATCH * NHEADS * NSEQ * HDIM];
__device__ __half g_att[MTOT * CDIM];                   // [B,N,C] fp16

__device__ __forceinline__ float fex2(float x) {
    float r;
    asm("ex2.approx.f32 %0, %1;" : "=f"(r) : "f"(x));
    return r;
}
__device__ __forceinline__ uint32_t pack_f16(float lo, float hi) {
    uint32_t r;
    asm("cvt.rn.f16x2.f32 %0, %1, %2;" : "=r"(r) : "f"(hi), "f"(lo));
    return r;
}
__device__ __forceinline__ void mma16h(float* c, const uint32_t* a,
                                       uint32_t b0, uint32_t b1) {
    asm volatile(
        "mma.sync.aligned.m16n8k16.row.col.f32.f16.f16.f32 "
        "{%0,%1,%2,%3}, {%4,%5,%6,%7}, {%8,%9}, {%0,%1,%2,%3};"
        : "+f"(c[0]), "+f"(c[1]), "+f"(c[2]), "+f"(c[3])
        : "r"(a[0]), "r"(a[1]), "r"(a[2]), "r"(a[3]), "r"(b0), "r"(b1));
}
__device__ __forceinline__ void ldsm4(uint32_t& r0, uint32_t& r1,
                                      uint32_t& r2, uint32_t& r3,
                                      uint32_t addr) {
    asm volatile(
        "ldmatrix.sync.aligned.m8n8.x4.shared.b16 {%0,%1,%2,%3}, [%4];"
        : "=r"(r0), "=r"(r1), "=r"(r2), "=r"(r3) : "r"(addr));
}
__device__ __forceinline__ void ldsm4t(uint32_t& r0, uint32_t& r1,
                                       uint32_t& r2, uint32_t& r3,
                                       uint32_t addr) {
    asm volatile(
        "ldmatrix.sync.aligned.m8n8.x4.trans.shared.b16 {%0,%1,%2,%3}, [%4];"
        : "=r"(r0), "=r"(r1), "=r"(r2), "=r"(r3) : "r"(addr));
}
__device__ __forceinline__ void cpasync16(uint32_t smem_addr, const void* gptr) {
    asm volatile("cp.async.cg.shared.global [%0], [%1], 16;"
                 :: "r"(smem_addr), "l"(gptr));
}
__device__ __forceinline__ void cp_commit() {
    asm volatile("cp.async.commit_group;" ::: "memory");
}
__device__ __forceinline__ void cp_wait0() {
    asm volatile("cp.async.wait_group 0;" ::: "memory");
}

// ---------------------------------------------------------------------------
// fp32 -> fp16 conversion pre-pass (vectorized float4 -> half4)
// ---------------------------------------------------------------------------
__global__ void cvt_h(const float* __restrict__ src, __half* __restrict__ dst,
                      int n4)
{
    const int i = blockIdx.x * blockDim.x + threadIdx.x;
    if (i < n4) {
        float4 v = ((const float4*)src)[i];
        uint2 u;
        u.x = pack_f16(v.x, v.y);
        u.y = pack_f16(v.z, v.w);
        *(uint2*)(dst + (size_t)i * 4) = u;
    }
}

// ---------------------------------------------------------------------------
// FP16 GEMM v2: out = (A[M,1024] @ W[1024,1024] + bias) * oscale
// fp16 A,W (pre-converted). 128x128x32 tiles, 256 threads, warp tile 64x32.
// cp.async 2-stage pipeline, one __syncthreads per k-iter.
// MODE 0: fp32 row-major [M,N]   MODE 1: fp16 scatter to [B,H,N,D]
// ---------------------------------------------------------------------------
#define AST2 40   // A smem row stride (halves): 80B -> conflict-free ldsm
#define BST  136  // B smem row stride (halves): 272B === 4 banks mod 32

template <int MODE>
__global__ __launch_bounds__(256, 2)
void gemm_h2(const __half* __restrict__ A, const __half* __restrict__ W,
             const float* __restrict__ bias, void* __restrict__ outv,
             float oscale)
{
    __shared__ __half Ah[2][128 * AST2];
    __shared__ __half Bh[2][32 * BST];

    const int tid = threadIdx.x, lane = tid & 31, warp = tid >> 5;
    const int g = lane >> 2, t = lane & 3;
    const int wm = (warp & 1) * 64, wn = (warp >> 1) * 32;
    const int row0 = blockIdx.y * 128, col0 = blockIdx.x * 128;

    const uint32_t ab0 = (uint32_t)__cvta_generic_to_shared(Ah[0]);
    const uint32_t ab1 = (uint32_t)__cvta_generic_to_shared(Ah[1]);
    const uint32_t bb0 = (uint32_t)__cvta_generic_to_shared(Bh[0]);
    const uint32_t bb1 = (uint32_t)__cvta_generic_to_shared(Bh[1]);

    // cp.async chunk assignments (16B chunks)
    // A tile: 128 rows x 4 chunks; B tile: 32 rows x 16 chunks
    const int ar0 = tid >> 2, ac0 = (tid & 3) * 8;        // chunk c = tid
    const int ar1 = (tid + 256) >> 2, ac1 = ac0;           // chunk c = tid+256
    const int br0 = tid >> 4, bc0 = (tid & 15) * 8;
    const int br1 = (tid + 256) >> 4, bc1 = bc0;

    auto stage = [&](int k0, int b) {
        const uint32_t abs_ = b ? ab1 : ab0;
        const uint32_t bbs_ = b ? bb1 : bb0;
        cpasync16(abs_ + (uint32_t)(ar0 * AST2 + ac0) * 2,
                  A + (size_t)(row0 + ar0) * CDIM + k0 + ac0);
        cpasync16(abs_ + (uint32_t)(ar1 * AST2 + ac1) * 2,
                  A + (size_t)(row0 + ar1) * CDIM + k0 + ac1);
        cpasync16(bbs_ + (uint32_t)(br0 * BST + bc0) * 2,
                  W + (size_t)(k0 + br0) * CDIM + col0 + bc0);
        cpasync16(bbs_ + (uint32_t)(br1 * BST + bc1) * 2,
                  W + (size_t)(k0 + br1) * CDIM + col0 + bc1);
        cp_commit();
    };

    // ldmatrix lane offsets
    const uint32_t afrag_row = (lane & 7) + 8 * ((lane >> 3) & 1);
    const uint32_t afrag_col = (lane >> 4) * 8;
    const uint32_t bfrag_row = lane & 15;
    const uint32_t bfrag_col = 8 * (lane >> 4);

    float acc[4][4][4];
#pragma unroll
    for (int i = 0; i < 4; i++)
#pragma unroll
        for (int j = 0; j < 4; j++)
#pragma unroll
            for (int v = 0; v < 4; v++) acc[i][j][v] = 0.f;

    stage(0, 0);

    int buf = 0;
    for (int it = 0; it < 32; it++) {
        cp_wait0();
        __syncthreads();
        if (it < 31) stage((it + 1) * 32, buf ^ 1);

        const uint32_t abase = buf ? ab1 : ab0;
        const uint32_t bbase = buf ? bb1 : bb0;
#pragma unroll
        for (int ks = 0; ks < 2; ks++) {
            uint32_t af[4][4];
#pragma unroll
            for (int mt = 0; mt < 4; mt++) {
                const uint32_t addr = abase +
                    (uint32_t)((wm + mt * 16 + afrag_row) * AST2 +
                               ks * 16 + afrag_col) * 2;
                ldsm4(af[mt][0], af[mt][1], af[mt][2], af[mt][3], addr);
            }
#pragma unroll
            for (int j = 0; j < 2; j++) {
                uint32_t r0, r1, r2, r3;
                const uint32_t addr = bbase +
                    (uint32_t)((ks * 16 + bfrag_row) * BST +
                               wn + j * 16 + bfrag_col) * 2;
                ldsm4t(r0, r1, r2, r3, addr);
#pragma unroll
                for (int mt = 0; mt < 4; mt++) {
                    mma16h(acc[mt][2 * j],     af[mt], r0, r1);
                    mma16h(acc[mt][2 * j + 1], af[mt], r2, r3);
                }
            }
        }
        buf ^= 1;
    }

    // epilogue
#pragma unroll
    for (int mt = 0; mt < 4; mt++) {
        const int r = row0 + wm + mt * 16 + g;
#pragma unroll
        for (int nt = 0; nt < 4; nt++) {
            const int c = col0 + wn + nt * 8 + 2 * t;
            const float bx = bias[c], by = bias[c + 1];
            const float v00 = (acc[mt][nt][0] + bx) * oscale;
            const float v01 = (acc[mt][nt][1] + by) * oscale;
            const float v10 = (acc[mt][nt][2] + bx) * oscale;
            const float v11 = (acc[mt][nt][3] + by) * oscale;
            if (MODE == 0) {
                float* out = (float*)outv;
                *(float2*)(out + (size_t)r * CDIM + c) = make_float2(v00, v01);
                *(float2*)(out + (size_t)(r + 8) * CDIM + c) = make_float2(v10, v11);
            } else {
                __half* out = (__half*)outv;
                const int h = c >> 6, d = c & 63;
                const int bi = r >> 11, ni = r & (NSEQ - 1);
                *(uint32_t*)(out + ((size_t)(bi * NHEADS + h) * NSEQ + ni) * HDIM + d) =
                    pack_f16(v00, v01);
                *(uint32_t*)(out + ((size_t)(bi * NHEADS + h) * NSEQ + ni + 8) * HDIM + d) =
                    pack_f16(v10, v11);
            }
        }
    }
}

// ---------------------------------------------------------------------------
// Flash attention v6 (fp16 in/out, fp32 accum):
//  - Q pre-scaled fp16 in gmem, staged raw, frags hoisted to registers
//  - K/V fp16 staged via cp.async, DOUBLE-BUFFERED (tile i+1 load overlaps
//    tile i compute); one __syncthreads per tile
//  - output written as fp16 (feeds fp16 O-proj GEMM)
// ---------------------------------------------------------------------------
#define QSTR 72   // halves

__global__ __launch_bounds__(256, 2)
void attn_h2(const __half* __restrict__ Qg, const __half* __restrict__ Kg,
             const __half* __restrict__ Vg, __half* __restrict__ att)
{
    extern __shared__ uint16_t smh[];
    uint16_t* Qh = smh;                        // [128][72]
    // K double buffers then V double buffers
    const int KV = 64 * QSTR;
    uint16_t* Kh = Qh + 128 * QSTR;            // [2][64][72]
    uint16_t* Vh = Kh + 2 * KV;                // [2][64][72]

    const int tid = threadIdx.x, lane = tid & 31, warp = tid >> 5;
    const int g = lane >> 2, t = lane & 3;
    const int bh = blockIdx.y;
    const int qb = blockIdx.x * 128;

    const __half* Q = Qg + (size_t)bh * NSEQ * HDIM;
    const __half* K = Kg + (size_t)bh * NSEQ * HDIM;
    const __half* V = Vg + (size_t)bh * NSEQ * HDIM;

    const uint32_t qbase = (uint32_t)__cvta_generic_to_shared(Qh);
    const uint32_t kbase = (uint32_t)__cvta_generic_to_shared(Kh);
    const uint32_t vbase = (uint32_t)__cvta_generic_to_shared(Vh);

    const uint32_t afrag_row = (lane & 7) + 8 * ((lane >> 3) & 1);
    const uint32_t afrag_col = (lane >> 4) * 8;
    const uint32_t bfrag_row = lane & 15;
    const uint32_t bfrag_col = 8 * (lane >> 4);

    // K/V tile staging via cp.async: 64 rows x 8 chunks each
    const int kr0 = tid >> 3, kc0 = (tid & 7) * 8;          // chunk c = tid
    const int kr1 = (tid + 256) >> 3, kc1 = kc0;            // chunk c = tid+256
    auto stage_kv = [&](int kt, int b) {
        const uint32_t kb_ = kbase + (uint32_t)(b * KV) * 2;
        const uint32_t vb_ = vbase + (uint32_t)(b * KV) * 2;
        cpasync16(kb_ + (uint32_t)(kr0 * QSTR + kc0) * 2,
                  K + (size_t)(kt + kr0) * HDIM + kc0);
        cpasync16(kb_ + (uint32_t)(kr1 * QSTR + kc1) * 2,
                  K + (size_t)(kt + kr1) * HDIM + kc1);
        cpasync16(vb_ + (uint32_t)(kr0 * QSTR + kc0) * 2,
                  V + (size_t)(kt + kr0) * HDIM + kc0);
        cpasync16(vb_ + (uint32_t)(kr1 * QSTR + kc1) * 2,
                  V + (size_t)(kt + kr1) * HDIM + kc1);
        cp_commit();
    };

    // issue first K/V tile, then stage Q (overlaps the cp.async)
    stage_kv(0, 0);
#pragma unroll
    for (int r = 0; r < 4; r++) {
        const int idx = tid + r * 256;       // 1024 chunks of 16B
        const int row = idx >> 3, cc = (idx & 7) * 8;
        *(uint4*)&Qh[row * QSTR + cc] =
            *(const uint4*)(Q + (size_t)(qb + row) * HDIM + cc);
    }
    __syncthreads();

    // hoist Q fragments (invariant over the k-loop)
    uint32_t aq[4][4];
#pragma unroll
    for (int dc = 0; dc < 4; dc++) {
        const uint32_t addr = qbase +
            (uint32_t)((warp * 16 + afrag_row) * QSTR + dc * 16 + afrag_col) * 2;
        ldsm4(aq[dc][0], aq[dc][1], aq[dc][2], aq[dc][3], addr);
    }

    float o[8][4];
#pragma unroll
    for (int b = 0; b < 8; b++)
#pragma unroll
        for (int c = 0; c < 4; c++) o[b][c] = 0.f;
    float mrow[2] = {-1e30f, -1e30f};
    float lrow[2] = {0.f, 0.f};

    int buf = 0;
    for (int it = 0; it < NSEQ / 64; it++) {
        cp_wait0();
        __syncthreads();
        if (it < NSEQ / 64 - 1) stage_kv((it + 1) * 64, buf ^ 1);

        const uint32_t kb = kbase + (uint32_t)(buf * KV) * 2;
        const uint32_t vb = vbase + (uint32_t)(buf * KV) * 2;

        // ---- S = Q @ K^T ----
        float s[8][4];
#pragma unroll
        for (int b = 0; b < 8; b++)
#pragma unroll
            for (int c = 0; c < 4; c++) s[b][c] = 0.f;

#pragma unroll
        for (int dc = 0; dc < 4; dc++) {
#pragma unroll
            for (int kp = 0; kp < 4; kp++) {
                uint32_t r0, r1, r2, r3;
                const uint32_t addr = kb +
                    (uint32_t)((kp * 16 + bfrag_row) * QSTR + dc * 16 + bfrag_col) * 2;
                ldsm4(r0, r1, r2, r3, addr);
                mma16h(s[2 * kp],     aq[dc], r0, r2);
                mma16h(s[2 * kp + 1], aq[dc], r1, r3);
            }
        }

        // ---- online softmax; P packed to fp16 in registers ----
        uint32_t pk[8][2];
        {
            float tl = -1e30f, th = -1e30f;
#pragma unroll
            for (int nt = 0; nt < 8; nt++) {
                tl = fmaxf(tl, fmaxf(s[nt][0], s[nt][1]));
                th = fmaxf(th, fmaxf(s[nt][2], s[nt][3]));
            }
            tl = fmaxf(tl, __shfl_xor_sync(0xffffffffu, tl, 1));
            tl = fmaxf(tl, __shfl_xor_sync(0xffffffffu, tl, 2));
            th = fmaxf(th, __shfl_xor_sync(0xffffffffu, th, 1));
            th = fmaxf(th, __shfl_xor_sync(0xffffffffu, th, 2));

            const float mlo = fmaxf(mrow[0], tl);
            const float mhi = fmaxf(mrow[1], th);
            const float alo = fex2(mrow[0] - mlo);
            const float ahi = fex2(mrow[1] - mhi);
            mrow[0] = mlo; mrow[1] = mhi;
            lrow[0] *= alo; lrow[1] *= ahi;
#pragma unroll
            for (int dt = 0; dt < 8; dt++) {
                o[dt][0] *= alo; o[dt][1] *= alo;
                o[dt][2] *= ahi; o[dt][3] *= ahi;
            }
#pragma unroll
            for (int nt = 0; nt < 8; nt++) {
                const float p0 = fex2(s[nt][0] - mlo);
                const float p1 = fex2(s[nt][1] - mlo);
                const float p2 = fex2(s[nt][2] - mhi);
                const float p3 = fex2(s[nt][3] - mhi);
                lrow[0] += p0 + p1;
                lrow[1] += p2 + p3;
                pk[nt][0] = pack_f16(p0, p1);
                pk[nt][1] = pack_f16(p2, p3);
            }
        }

        // ---- O += P @ V ----
#pragma unroll
        for (int kc = 0; kc < 4; kc++) {
            uint32_t ap[4];
            ap[0] = pk[2 * kc][0];
            ap[1] = pk[2 * kc][1];
            ap[2] = pk[2 * kc + 1][0];
            ap[3] = pk[2 * kc + 1][1];
#pragma unroll
            for (int j = 0; j < 4; j++) {
                uint32_t r0, r1, r2, r3;
                const uint32_t addr = vb +
                    (uint32_t)((kc * 16 + bfrag_row) * QSTR + j * 16 + bfrag_col) * 2;
                ldsm4t(r0, r1, r2, r3, addr);
                mma16h(o[2 * j],     ap, r0, r1);
                mma16h(o[2 * j + 1], ap, r2, r3);
            }
        }
        buf ^= 1;
    }

    // finalize: reduce row sums, normalize, store fp16
    const int b = bh >> 4, h = bh & 15;
    float l0 = lrow[0], l1 = lrow[1];
    l0 += __shfl_xor_sync(0xffffffffu, l0, 1);
    l0 += __shfl_xor_sync(0xffffffffu, l0, 2);
    l1 += __shfl_xor_sync(0xffffffffu, l1, 1);
    l1 += __shfl_xor_sync(0xffffffffu, l1, 2);
    const float i0 = 1.f / l0, i1 = 1.f / l1;
    const int qg = qb + warp * 16 + g;
#pragma unroll
    for (int nt = 0; nt < 8; nt++) {
        const int col = h * 64 + nt * 8 + 2 * t;
        *(uint32_t*)(att + (size_t)(b * NSEQ + qg) * CDIM + col) =
            pack_f16(o[nt][0] * i0, o[nt][1] * i0);
        *(uint32_t*)(att + (size_t)(b * NSEQ + qg + 8) * CDIM + col) =
            pack_f16(o[nt][2] * i1, o[nt][3] * i1);
    }
}

// ---------------------------------------------------------------------------

extern "C" void kernel_launch(void* const* d_in, const int* in_sizes, int n_in,
                              void* d_out, int out_size)
{
    const float* x  = (const float*)d_in[0];
    const float* Wq = (const float*)d_in[1];
    const float* bq = (const float*)d_in[2];
    const float* Wk = (const float*)d_in[3];
    const float* bk = (const float*)d_in[4];
    const float* Wv = (const float*)d_in[5];
    const float* bv = (const float*)d_in[6];
    const float* Wo = (const float*)d_in[7];
    const float* bo = (const float*)d_in[8];
    float* out = (float*)d_out;

    __half *xh, *Wqh, *Wkh, *Wvh, *Woh, *Qp, *Kp, *Vp, *Ap;
    cudaGetSymbolAddress((void**)&xh,  g_xh);
    cudaGetSymbolAddress((void**)&Wqh, g_Wq);
    cudaGetSymbolAddress((void**)&Wkh, g_Wk);
    cudaGetSymbolAddress((void**)&Wvh, g_Wv);
    cudaGetSymbolAddress((void**)&Woh, g_Wo);
    cudaGetSymbolAddress((void**)&Qp,  g_Q);
    cudaGetSymbolAddress((void**)&Kp,  g_K);
    cudaGetSymbolAddress((void**)&Vp,  g_V);
    cudaGetSymbolAddress((void**)&Ap,  g_att);

    // pre-pass: fp32 -> fp16
    const int xw4 = MTOT * CDIM / 4, ww4 = CDIM * CDIM / 4;
    cvt_h<<<(xw4 + 255) / 256, 256>>>(x,  xh,  xw4);
    cvt_h<<<(ww4 + 255) / 256, 256>>>(Wq, Wqh, ww4);
    cvt_h<<<(ww4 + 255) / 256, 256>>>(Wk, Wkh, ww4);
    cvt_h<<<(ww4 + 255) / 256, 256>>>(Wv, Wvh, ww4);
    cvt_h<<<(ww4 + 255) / 256, 256>>>(Wo, Woh, ww4);

    const dim3 ggrid(CDIM / 128, MTOT / 128);  // (8, 64)
    const float qscale = 0.125f * 1.4426950408889634f;  // 1/sqrt(D) * log2(e)

    gemm_h2<1><<<ggrid, 256>>>(xh, Wqh, bq, Qp, qscale);
    gemm_h2<1><<<ggrid, 256>>>(xh, Wkh, bk, Kp, 1.f);
    gemm_h2<1><<<ggrid, 256>>>(xh, Wvh, bv, Vp, 1.f);

    const int att_smem = (128 * QSTR + 4 * 64 * QSTR) * 2;  // 55296 B
    cudaFuncSetAttribute(attn_h2,
                         cudaFuncAttributeMaxDynamicSharedMemorySize, att_smem);
    attn_h2<<<dim3(NSEQ / 128, BATCH * NHEADS), 256, att_smem>>>(Qp, Kp, Vp, Ap);

    gemm_h2<0><<<ggrid, 256>>>(Ap, Woh, bo, out, 1.f);
}

// round 8
// speedup vs baseline: 8.5675x; 1.0447x over previous
#include <cuda_runtime.h>
#include <cuda_fp16.h>
#include <math.h>
#include <stdint.h>

#define BATCH   4
#define NSEQ    2048
#define CDIM    1024
#define NHEADS  16
#define HDIM    64
#define MTOT    (BATCH * NSEQ)   // 8192

// Scratch (allocation-free rule: __device__ globals)
__device__ __half g_xh[MTOT * CDIM];                    // x in fp16
__device__ __half g_Wqkv[CDIM * 3 * CDIM];              // [1024][3072] fp16
__device__ __half g_Wo[CDIM * CDIM];
__device__ __half g_Q[BATCH * NHEADS * NSEQ * HDIM];    // [B,H,N,D] (pre-scaled)
__device__ __half g_K[BATCH * NHEADS * NSEQ * HDIM];
__device__ __half g_V[BATCH * NHEADS * NSEQ * HDIM];
__device__ __half g_att[MTOT * CDIM];                   // [B,N,C] fp16

__device__ __forceinline__ float fex2(float x) {
    float r;
    asm("ex2.approx.f32 %0, %1;" : "=f"(r) : "f"(x));
    return r;
}
__device__ __forceinline__ uint32_t pack_f16(float lo, float hi) {
    uint32_t r;
    asm("cvt.rn.f16x2.f32 %0, %1, %2;" : "=r"(r) : "f"(hi), "f"(lo));
    return r;
}
__device__ __forceinline__ void mma16h(float* c, const uint32_t* a,
                                       uint32_t b0, uint32_t b1) {
    asm volatile(
        "mma.sync.aligned.m16n8k16.row.col.f32.f16.f16.f32 "
        "{%0,%1,%2,%3}, {%4,%5,%6,%7}, {%8,%9}, {%0,%1,%2,%3};"
        : "+f"(c[0]), "+f"(c[1]), "+f"(c[2]), "+f"(c[3])
        : "r"(a[0]), "r"(a[1]), "r"(a[2]), "r"(a[3]), "r"(b0), "r"(b1));
}
__device__ __forceinline__ void ldsm4(uint32_t& r0, uint32_t& r1,
                                      uint32_t& r2, uint32_t& r3,
                                      uint32_t addr) {
    asm volatile(
        "ldmatrix.sync.aligned.m8n8.x4.shared.b16 {%0,%1,%2,%3}, [%4];"
        : "=r"(r0), "=r"(r1), "=r"(r2), "=r"(r3) : "r"(addr));
}
__device__ __forceinline__ void ldsm4t(uint32_t& r0, uint32_t& r1,
                                       uint32_t& r2, uint32_t& r3,
                                       uint32_t addr) {
    asm volatile(
        "ldmatrix.sync.aligned.m8n8.x4.trans.shared.b16 {%0,%1,%2,%3}, [%4];"
        : "=r"(r0), "=r"(r1), "=r"(r2), "=r"(r3) : "r"(addr));
}
__device__ __forceinline__ void cpasync16(uint32_t smem_addr, const void* gptr) {
    asm volatile("cp.async.cg.shared.global [%0], [%1], 16;"
                 :: "r"(smem_addr), "l"(gptr));
}
__device__ __forceinline__ void cp_commit() {
    asm volatile("cp.async.commit_group;" ::: "memory");
}
__device__ __forceinline__ void cp_wait0() {
    asm volatile("cp.async.wait_group 0;" ::: "memory");
}
__device__ __forceinline__ void cp_wait1() {
    asm volatile("cp.async.wait_group 1;" ::: "memory");
}

// ---------------------------------------------------------------------------
// Conversion pre-passes
// ---------------------------------------------------------------------------
__global__ void cvt_h(const float* __restrict__ src, __half* __restrict__ dst,
                      int n4)
{
    const int i = blockIdx.x * blockDim.x + threadIdx.x;
    if (i < n4) {
        float4 v = ((const float4*)src)[i];
        uint2 u;
        u.x = pack_f16(v.x, v.y);
        u.y = pack_f16(v.z, v.w);
        *(uint2*)(dst + (size_t)i * 4) = u;
    }
}

// 4 weights in one launch: Wq/Wk/Wv -> concat [1024][3072]; Wo -> [1024][1024]
__global__ void cvt_w4(const float* __restrict__ Wq, const float* __restrict__ Wk,
                       const float* __restrict__ Wv, const float* __restrict__ Wo,
                       __half* __restrict__ Wqkv, __half* __restrict__ Woh)
{
    const int i = blockIdx.x * blockDim.x + threadIdx.x;   // 0 .. 262143
    const int y = blockIdx.y;
    const float* src = (y == 0) ? Wq : (y == 1) ? Wk : (y == 2) ? Wv : Wo;
    float4 v = ((const float4*)src)[i];
    uint2 u;
    u.x = pack_f16(v.x, v.y);
    u.y = pack_f16(v.z, v.w);
    const int row = i >> 8;           // / 256  (1024 cols / 4)
    const int c4  = i & 255;
    if (y < 3)
        *(uint2*)(Wqkv + (size_t)row * 3072 + y * 1024 + c4 * 4) = u;
    else
        *(uint2*)(Woh + (size_t)row * 1024 + c4 * 4) = u;
}

// ---------------------------------------------------------------------------
// FP16 GEMM, 3-stage cp.async pipeline.
// 128x128x32 tiles, 256 threads, warp tile 64x32.
// MODE 0: W stride 1024, fp32 out row-major (O projection)
// MODE 1: W stride 3072 (fused QKV), fp16 scatter to [B,H,N,D] per section
// ---------------------------------------------------------------------------
#define AST2 40   // A smem row stride (halves)
#define BST  136  // B smem row stride (halves)

template <int MODE>
__global__ __launch_bounds__(256, 2)
void gemm_h3(const __half* __restrict__ A, const __half* __restrict__ W,
             const float* __restrict__ bq, const float* __restrict__ bk,
             const float* __restrict__ bv,
             void* __restrict__ o0, void* __restrict__ o1, void* __restrict__ o2,
             float qsc)
{
    const int WS = (MODE == 1) ? 3 * CDIM : CDIM;   // W row stride

    __shared__ __half Ah[3][128 * AST2];
    __shared__ __half Bh[3][32 * BST];

    const int tid = threadIdx.x, lane = tid & 31, warp = tid >> 5;
    const int g = lane >> 2, t = lane & 3;
    const int wm = (warp & 1) * 64, wn = (warp >> 1) * 32;
    const int row0 = blockIdx.y * 128, col0 = blockIdx.x * 128;

    // section select (MODE 1)
    const int sec = col0 >> 10;            // 0,1,2
    const int cloc = col0 & 1023;
    const float* bias = (MODE == 0) ? bq : (sec == 0) ? bq : (sec == 1) ? bk : bv;
    const float oscale = (MODE == 1 && sec == 0) ? qsc : 1.f;

    uint32_t abase[3], bbase[3];
#pragma unroll
    for (int s = 0; s < 3; s++) {
        abase[s] = (uint32_t)__cvta_generic_to_shared(Ah[s]);
        bbase[s] = (uint32_t)__cvta_generic_to_shared(Bh[s]);
    }

    const int ar0 = tid >> 2, ac0 = (tid & 3) * 8;
    const int br0 = tid >> 4, bc0 = (tid & 15) * 8;

    auto stage = [&](int k0, int s) {
        cpasync16(abase[s] + (uint32_t)(ar0 * AST2 + ac0) * 2,
                  A + (size_t)(row0 + ar0) * CDIM + k0 + ac0);
        cpasync16(abase[s] + (uint32_t)((ar0 + 64) * AST2 + ac0) * 2,
                  A + (size_t)(row0 + ar0 + 64) * CDIM + k0 + ac0);
        cpasync16(bbase[s] + (uint32_t)(br0 * BST + bc0) * 2,
                  W + (size_t)(k0 + br0) * WS + col0 + bc0);
        cpasync16(bbase[s] + (uint32_t)((br0 + 16) * BST + bc0) * 2,
                  W + (size_t)(k0 + br0 + 16) * WS + col0 + bc0);
        cp_commit();
    };

    const uint32_t afrag_row = (lane & 7) + 8 * ((lane >> 3) & 1);
    const uint32_t afrag_col = (lane >> 4) * 8;
    const uint32_t bfrag_row = lane & 15;
    const uint32_t bfrag_col = 8 * (lane >> 4);

    float acc[4][4][4];
#pragma unroll
    for (int i = 0; i < 4; i++)
#pragma unroll
        for (int j = 0; j < 4; j++)
#pragma unroll
            for (int v = 0; v < 4; v++) acc[i][j][v] = 0.f;

    stage(0, 0);
    stage(32, 1);

    for (int it = 0; it < 32; it++) {
        if (it < 31) cp_wait1(); else cp_wait0();
        __syncthreads();
        if (it + 2 < 32) stage((it + 2) * 32, (it + 2) % 3);

        const int s = it % 3;
#pragma unroll
        for (int ks = 0; ks < 2; ks++) {
            uint32_t af[4][4];
#pragma unroll
            for (int mt = 0; mt < 4; mt++) {
                const uint32_t addr = abase[s] +
                    (uint32_t)((wm + mt * 16 + afrag_row) * AST2 +
                               ks * 16 + afrag_col) * 2;
                ldsm4(af[mt][0], af[mt][1], af[mt][2], af[mt][3], addr);
            }
#pragma unroll
            for (int j = 0; j < 2; j++) {
                uint32_t r0, r1, r2, r3;
                const uint32_t addr = bbase[s] +
                    (uint32_t)((ks * 16 + bfrag_row) * BST +
                               wn + j * 16 + bfrag_col) * 2;
                ldsm4t(r0, r1, r2, r3, addr);
#pragma unroll
                for (int mt = 0; mt < 4; mt++) {
                    mma16h(acc[mt][2 * j],     af[mt], r0, r1);
                    mma16h(acc[mt][2 * j + 1], af[mt], r2, r3);
                }
            }
        }
    }

    // epilogue
    void* outsec = (MODE == 0) ? o0 : (sec == 0) ? o0 : (sec == 1) ? o1 : o2;
#pragma unroll
    for (int mt = 0; mt < 4; mt++) {
        const int r = row0 + wm + mt * 16 + g;
#pragma unroll
        for (int nt = 0; nt < 4; nt++) {
            const int c = wn + nt * 8 + 2 * t;    // 0..127 within tile
            const int cb = (MODE == 0) ? col0 + c : cloc + c;
            const float bx = bias[cb], by = bias[cb + 1];
            const float v00 = (acc[mt][nt][0] + bx) * oscale;
            const float v01 = (acc[mt][nt][1] + by) * oscale;
            const float v10 = (acc[mt][nt][2] + bx) * oscale;
            const float v11 = (acc[mt][nt][3] + by) * oscale;
            if (MODE == 0) {
                float* out = (float*)outsec;
                *(float2*)(out + (size_t)r * CDIM + col0 + c) = make_float2(v00, v01);
                *(float2*)(out + (size_t)(r + 8) * CDIM + col0 + c) = make_float2(v10, v11);
            } else {
                __half* out = (__half*)outsec;
                const int h = cb >> 6, d = cb & 63;
                const int bi = r >> 11, ni = r & (NSEQ - 1);
                *(uint32_t*)(out + ((size_t)(bi * NHEADS + h) * NSEQ + ni) * HDIM + d) =
                    pack_f16(v00, v01);
                *(uint32_t*)(out + ((size_t)(bi * NHEADS + h) * NSEQ + ni + 8) * HDIM + d) =
                    pack_f16(v10, v11);
            }
        }
    }
}

// ---------------------------------------------------------------------------
// Flash attention v7: 3-stage cp.async K/V pipeline (two tiles in flight).
// ---------------------------------------------------------------------------
#define QSTR 72   // halves

__global__ __launch_bounds__(256, 2)
void attn_h3(const __half* __restrict__ Qg, const __half* __restrict__ Kg,
             const __half* __restrict__ Vg, __half* __restrict__ att)
{
    extern __shared__ uint16_t smh[];
    uint16_t* Qh = smh;                        // [128][72]
    const int KV = 64 * QSTR;
    uint16_t* Kh = Qh + 128 * QSTR;            // [3][64][72]
    uint16_t* Vh = Kh + 3 * KV;                // [3][64][72]

    const int tid = threadIdx.x, lane = tid & 31, warp = tid >> 5;
    const int g = lane >> 2, t = lane & 3;
    const int bh = blockIdx.y;
    const int qb = blockIdx.x * 128;

    const __half* Q = Qg + (size_t)bh * NSEQ * HDIM;
    const __half* K = Kg + (size_t)bh * NSEQ * HDIM;
    const __half* V = Vg + (size_t)bh * NSEQ * HDIM;

    const uint32_t qbase = (uint32_t)__cvta_generic_to_shared(Qh);
    const uint32_t kbase = (uint32_t)__cvta_generic_to_shared(Kh);
    const uint32_t vbase = (uint32_t)__cvta_generic_to_shared(Vh);

    const uint32_t afrag_row = (lane & 7) + 8 * ((lane >> 3) & 1);
    const uint32_t afrag_col = (lane >> 4) * 8;
    const uint32_t bfrag_row = lane & 15;
    const uint32_t bfrag_col = 8 * (lane >> 4);

    const int kr0 = tid >> 3, kc0 = (tid & 7) * 8;
    auto stage_kv = [&](int kt, int s) {
        const uint32_t kb_ = kbase + (uint32_t)(s * KV) * 2;
        const uint32_t vb_ = vbase + (uint32_t)(s * KV) * 2;
        cpasync16(kb_ + (uint32_t)(kr0 * QSTR + kc0) * 2,
                  K + (size_t)(kt + kr0) * HDIM + kc0);
        cpasync16(kb_ + (uint32_t)((kr0 + 32) * QSTR + kc0) * 2,
                  K + (size_t)(kt + kr0 + 32) * HDIM + kc0);
        cpasync16(vb_ + (uint32_t)(kr0 * QSTR + kc0) * 2,
                  V + (size_t)(kt + kr0) * HDIM + kc0);
        cpasync16(vb_ + (uint32_t)((kr0 + 32) * QSTR + kc0) * 2,
                  V + (size_t)(kt + kr0 + 32) * HDIM + kc0);
        cp_commit();
    };

    stage_kv(0, 0);
    stage_kv(64, 1);
    // stage Q (plain loads, overlap the cp.asyncs)
#pragma unroll
    for (int r = 0; r < 4; r++) {
        const int idx = tid + r * 256;
        const int row = idx >> 3, cc = (idx & 7) * 8;
        *(uint4*)&Qh[row * QSTR + cc] =
            *(const uint4*)(Q + (size_t)(qb + row) * HDIM + cc);
    }
    __syncthreads();

    uint32_t aq[4][4];
#pragma unroll
    for (int dc = 0; dc < 4; dc++) {
        const uint32_t addr = qbase +
            (uint32_t)((warp * 16 + afrag_row) * QSTR + dc * 16 + afrag_col) * 2;
        ldsm4(aq[dc][0], aq[dc][1], aq[dc][2], aq[dc][3], addr);
    }

    float o[8][4];
#pragma unroll
    for (int b = 0; b < 8; b++)
#pragma unroll
        for (int c = 0; c < 4; c++) o[b][c] = 0.f;
    float mrow[2] = {-1e30f, -1e30f};
    float lrow[2] = {0.f, 0.f};

    const int NT = NSEQ / 64;   // 32
    for (int it = 0; it < NT; it++) {
        if (it < NT - 1) cp_wait1(); else cp_wait0();
        __syncthreads();
        if (it + 2 < NT) stage_kv((it + 2) * 64, (it + 2) % 3);

        const int s = it % 3;
        const uint32_t kb = kbase + (uint32_t)(s * KV) * 2;
        const uint32_t vb = vbase + (uint32_t)(s * KV) * 2;

        // ---- S = Q @ K^T ----
        float sreg[8][4];
#pragma unroll
        for (int b = 0; b < 8; b++)
#pragma unroll
            for (int c = 0; c < 4; c++) sreg[b][c] = 0.f;

#pragma unroll
        for (int dc = 0; dc < 4; dc++) {
#pragma unroll
            for (int kp = 0; kp < 4; kp++) {
                uint32_t r0, r1, r2, r3;
                const uint32_t addr = kb +
                    (uint32_t)((kp * 16 + bfrag_row) * QSTR + dc * 16 + bfrag_col) * 2;
                ldsm4(r0, r1, r2, r3, addr);
                mma16h(sreg[2 * kp],     aq[dc], r0, r2);
                mma16h(sreg[2 * kp + 1], aq[dc], r1, r3);
            }
        }

        // ---- online softmax; P packed fp16 in registers ----
        uint32_t pk[8][2];
        {
            float tl = -1e30f, th = -1e30f;
#pragma unroll
            for (int nt = 0; nt < 8; nt++) {
                tl = fmaxf(tl, fmaxf(sreg[nt][0], sreg[nt][1]));
                th = fmaxf(th, fmaxf(sreg[nt][2], sreg[nt][3]));
            }
            tl = fmaxf(tl, __shfl_xor_sync(0xffffffffu, tl, 1));
            tl = fmaxf(tl, __shfl_xor_sync(0xffffffffu, tl, 2));
            th = fmaxf(th, __shfl_xor_sync(0xffffffffu, th, 1));
            th = fmaxf(th, __shfl_xor_sync(0xffffffffu, th, 2));

            const float mlo = fmaxf(mrow[0], tl);
            const float mhi = fmaxf(mrow[1], th);
            const float alo = fex2(mrow[0] - mlo);
            const float ahi = fex2(mrow[1] - mhi);
            mrow[0] = mlo; mrow[1] = mhi;
            lrow[0] *= alo; lrow[1] *= ahi;
#pragma unroll
            for (int dt = 0; dt < 8; dt++) {
                o[dt][0] *= alo; o[dt][1] *= alo;
                o[dt][2] *= ahi; o[dt][3] *= ahi;
            }
#pragma unroll
            for (int nt = 0; nt < 8; nt++) {
                const float p0 = fex2(sreg[nt][0] - mlo);
                const float p1 = fex2(sreg[nt][1] - mlo);
                const float p2 = fex2(sreg[nt][2] - mhi);
                const float p3 = fex2(sreg[nt][3] - mhi);
                lrow[0] += p0 + p1;
                lrow[1] += p2 + p3;
                pk[nt][0] = pack_f16(p0, p1);
                pk[nt][1] = pack_f16(p2, p3);
            }
        }

        // ---- O += P @ V ----
#pragma unroll
        for (int kc = 0; kc < 4; kc++) {
            uint32_t ap[4];
            ap[0] = pk[2 * kc][0];
            ap[1] = pk[2 * kc][1];
            ap[2] = pk[2 * kc + 1][0];
            ap[3] = pk[2 * kc + 1][1];
#pragma unroll
            for (int j = 0; j < 4; j++) {
                uint32_t r0, r1, r2, r3;
                const uint32_t addr = vb +
                    (uint32_t)((kc * 16 + bfrag_row) * QSTR + j * 16 + bfrag_col) * 2;
                ldsm4t(r0, r1, r2, r3, addr);
                mma16h(o[2 * j],     ap, r0, r1);
                mma16h(o[2 * j + 1], ap, r2, r3);
            }
        }
    }

    // finalize
    const int b = bh >> 4, h = bh & 15;
    float l0 = lrow[0], l1 = lrow[1];
    l0 += __shfl_xor_sync(0xffffffffu, l0, 1);
    l0 += __shfl_xor_sync(0xffffffffu, l0, 2);
    l1 += __shfl_xor_sync(0xffffffffu, l1, 1);
    l1 += __shfl_xor_sync(0xffffffffu, l1, 2);
    const float i0 = 1.f / l0, i1 = 1.f / l1;
    const int qg = qb + warp * 16 + g;
#pragma unroll
    for (int nt = 0; nt < 8; nt++) {
        const int col = h * 64 + nt * 8 + 2 * t;
        *(uint32_t*)(att + (size_t)(b * NSEQ + qg) * CDIM + col) =
            pack_f16(o[nt][0] * i0, o[nt][1] * i0);
        *(uint32_t*)(att + (size_t)(b * NSEQ + qg + 8) * CDIM + col) =
            pack_f16(o[nt][2] * i1, o[nt][3] * i1);
    }
}

// ---------------------------------------------------------------------------

extern "C" void kernel_launch(void* const* d_in, const int* in_sizes, int n_in,
                              void* d_out, int out_size)
{
    const float* x  = (const float*)d_in[0];
    const float* Wq = (const float*)d_in[1];
    const float* bq = (const float*)d_in[2];
    const float* Wk = (const float*)d_in[3];
    const float* bk = (const float*)d_in[4];
    const float* Wv = (const float*)d_in[5];
    const float* bv = (const float*)d_in[6];
    const float* Wo = (const float*)d_in[7];
    const float* bo = (const float*)d_in[8];
    float* out = (float*)d_out;

    __half *xh, *Wqkv, *Woh, *Qp, *Kp, *Vp, *Ap;
    cudaGetSymbolAddress((void**)&xh,   g_xh);
    cudaGetSymbolAddress((void**)&Wqkv, g_Wqkv);
    cudaGetSymbolAddress((void**)&Woh,  g_Wo);
    cudaGetSymbolAddress((void**)&Qp,   g_Q);
    cudaGetSymbolAddress((void**)&Kp,   g_K);
    cudaGetSymbolAddress((void**)&Vp,   g_V);
    cudaGetSymbolAddress((void**)&Ap,   g_att);

    // pre-pass: fp32 -> fp16 (x; 4 weights batched)
    const int xw4 = MTOT * CDIM / 4, ww4 = CDIM * CDIM / 4;
    cvt_h<<<(xw4 + 255) / 256, 256>>>(x, xh, xw4);
    cvt_w4<<<dim3(ww4 / 256, 4), 256>>>(Wq, Wk, Wv, Wo, Wqkv, Woh);

    const float qscale = 0.125f * 1.4426950408889634f;  // 1/sqrt(D) * log2(e)

    // fused QKV projection: N = 3072
    gemm_h3<1><<<dim3(3 * CDIM / 128, MTOT / 128), 256>>>(
        xh, Wqkv, bq, bk, bv, Qp, Kp, Vp, qscale);

    // attention
    const int att_smem = (128 * QSTR + 6 * 64 * QSTR) * 2;  // 73728 B
    cudaFuncSetAttribute(attn_h3,
                         cudaFuncAttributeMaxDynamicSharedMemorySize, att_smem);
    attn_h3<<<dim3(NSEQ / 128, BATCH * NHEADS), 256, att_smem>>>(Qp, Kp, Vp, Ap);

    // output projection
    gemm_h3<0><<<dim3(CDIM / 128, MTOT / 128), 256>>>(
        Ap, Woh, bo, nullptr, nullptr, out, nullptr, nullptr, 1.f);
}